// round 15
// baseline (speedup 1.0000x reference)
#include <cuda_runtime.h>
#include <cuda_bf16.h>
#include <cstdint>

#define BSZ  1024
#define TT   32
#define AD   224
#define HID  256
#define VOCAB 29
#define OUT_LEN 25

// ---------------- scratch (device globals) ----------------
__device__ float g_y1[BSZ*4*192*28];
__device__ float g_y2[BSZ*16*96*14];
__device__ float g_y3[BSZ*16*32*7];
__device__ float g_y5[BSZ*TT*AD];
__device__ __align__(16) float g_xW[BSZ*TT*896];
__device__ __align__(16) float g_y8[BSZ*TT*AD];
__device__ float g_escore[BSZ*TT];
__device__ float g_c [BSZ*AD];
__device__ float g_dh[BSZ*HID];
__device__ float g_dc[BSZ*HID];
__device__ __align__(16) float g_dhh[OUT_LEN][BSZ*HID];
// pre-split activations (bf16 hi/lo pairs packed as u32)
__device__ __align__(16) uint32_t g_Y5h[BSZ*TT*112], g_Y5l[BSZ*TT*112];
__device__ __align__(16) uint32_t g_Hh[2*BSZ*112],   g_Hl[2*BSZ*112];
__device__ __align__(16) uint32_t g_Ch[2*BSZ*240],   g_Cl[2*BSZ*240];
// pre-split weights, gate-interleaved rows
__device__ __align__(16) uint32_t g_WihH[896*112], g_WihL[896*112];
__device__ __align__(16) uint32_t g_WhhH[896*112], g_WhhL[896*112];
__device__ __align__(16) uint32_t g_WdH[1024*240], g_WdL[1024*240];
__device__ __align__(16) float g_bsE[896], g_bsD[1024];

__device__ __forceinline__ float sigm(float x){
    return __fdividef(1.0f, 1.0f + __expf(-x));
}
__device__ __forceinline__ void ffma4p(float4& a, const float4& x, const float4& w){
    unsigned long long* ap = reinterpret_cast<unsigned long long*>(&a);
    const unsigned long long* xp = reinterpret_cast<const unsigned long long*>(&x);
    const unsigned long long* wp = reinterpret_cast<const unsigned long long*>(&w);
    asm("fma.rn.f32x2 %0, %1, %2, %0;" : "+l"(ap[0]) : "l"(xp[0]), "l"(wp[0]));
    asm("fma.rn.f32x2 %0, %1, %2, %0;" : "+l"(ap[1]) : "l"(xp[1]), "l"(wp[1]));
}
__device__ __forceinline__ float hsum4(float4 a){ return a.x+a.y+a.z+a.w; }
__device__ __forceinline__ void splitpair(float x, float y, uint32_t& hi, uint32_t& lo){
    __nv_bfloat162 h = __floats2bfloat162_rn(x, y);
    __nv_bfloat162 l = __floats2bfloat162_rn(x - __bfloat162float(h.x), y - __bfloat162float(h.y));
    hi = *reinterpret_cast<uint32_t*>(&h);
    lo = *reinterpret_cast<uint32_t*>(&l);
}

// =====================  CONV STACK (exact R10/R12 versions)  =====================
__global__ __launch_bounds__(256) void conv1_k(const float* __restrict__ x,
        const float* __restrict__ cw, const float* __restrict__ cb, float* __restrict__ out){
    __shared__ float xin[66*30];
    __shared__ float w_s[36];
    __shared__ float b_s[4];
    int b = blockIdx.x/6, pho0 = (blockIdx.x%6)*32;
    int tid = threadIdx.x, lane = tid&31, warp = tid>>5;
    for(int f=tid; f<66*30; f+=256){
        int rr=f/30, cc=f%30;
        int gr=pho0*2-1+rr, gc=cc-1;
        float v=0.f;
        if(gr>=0 && gr<384 && gc>=0 && gc<28) v = x[((size_t)b*384+gr)*28+gc];
        xin[f]=v;
    }
    if(tid<36) w_s[tid]=cw[tid];
    if(tid<4)  b_s[tid]=cb[tid];
    __syncthreads();
    int wo = min(lane,27);
    for(int it=warp; it<128; it+=8){
        int oc=it>>5, ph=it&31;
        float wr[9];
        #pragma unroll
        for(int k=0;k<9;k++) wr[k]=w_s[oc*9+k];
        float bv=b_s[oc], s0=bv, s1=bv;
        #pragma unroll
        for(int kw=0;kw<3;kw++){
            float X[4];
            #pragma unroll
            for(int r=0;r<4;r++) X[r]=xin[(2*ph+r)*30+wo+kw];
            #pragma unroll
            for(int kh=0;kh<3;kh++){
                s0=fmaf(X[kh],  wr[kh*3+kw],s0);
                s1=fmaf(X[kh+1],wr[kh*3+kw],s1);
            }
        }
        float m = fmaxf(fmaxf(s0,0.f), fmaxf(s1,0.f));
        if(lane<28) out[((size_t)(b*4+oc)*192+pho0+ph)*28+wo]=m;
    }
}

__global__ __launch_bounds__(256) void conv2_k(const float* __restrict__ in,
        const float* __restrict__ cw, const float* __restrict__ cb, float* __restrict__ out){
    __shared__ float4 xin[34*30];
    __shared__ float4 w_s[144];
    __shared__ float  b_s[16];
    int b = blockIdx.x/6, pho0 = (blockIdx.x%6)*16;
    int tid = threadIdx.x, lane = tid&31, warp = tid>>5;
    for(int f=tid; f<34*30; f+=256){
        int rr=f/30, cc=f%30;
        int gr=pho0*2-1+rr, gc=cc-1;
        float4 v={0,0,0,0};
        if(gr>=0 && gr<192 && gc>=0 && gc<28){
            const float* p = in + ((size_t)b*4*192+gr)*28+gc;
            v.x=p[0]; v.y=p[192*28]; v.z=p[2*192*28]; v.w=p[3*192*28];
        }
        xin[f]=v;
    }
    for(int f=tid; f<144; f+=256){
        int oc=f/9, k=f%9;
        float4 v; v.x=cw[(oc*4+0)*9+k]; v.y=cw[(oc*4+1)*9+k];
                  v.z=cw[(oc*4+2)*9+k]; v.w=cw[(oc*4+3)*9+k];
        w_s[f]=v;
    }
    if(tid<16) b_s[tid]=cb[tid];
    __syncthreads();
    int wc = min(lane,27);
    int oc0 = warp, oc1 = warp+8;
    float bv0 = b_s[oc0], bv1 = b_s[oc1];
    #pragma unroll 1
    for(int pp=0; pp<8; pp++){
        float4 a[2][4];
        #pragma unroll
        for(int o=0;o<2;o++)
            #pragma unroll
            for(int r=0;r<4;r++) a[o][r]=make_float4(0,0,0,0);
        #pragma unroll
        for(int kw=0;kw<3;kw++){
            float4 X[6];
            #pragma unroll
            for(int r=0;r<6;r++) X[r]=xin[(pp*4+r)*30+wc+kw];
            #pragma unroll
            for(int kh=0;kh<3;kh++){
                float4 w0=w_s[oc0*9+kh*3+kw];
                float4 w1=w_s[oc1*9+kh*3+kw];
                ffma4p(a[0][0],X[kh],w0); ffma4p(a[0][1],X[kh+1],w0);
                ffma4p(a[0][2],X[kh+2],w0); ffma4p(a[0][3],X[kh+3],w0);
                ffma4p(a[1][0],X[kh],w1); ffma4p(a[1][1],X[kh+1],w1);
                ffma4p(a[1][2],X[kh+2],w1); ffma4p(a[1][3],X[kh+3],w1);
            }
        }
        #pragma unroll
        for(int o=0;o<2;o++){
            int oc = o ? oc1 : oc0;
            float bv = o ? bv1 : bv0;
            float s0=hsum4(a[o][0])+bv, s1=hsum4(a[o][1])+bv;
            float s2=hsum4(a[o][2])+bv, s3=hsum4(a[o][3])+bv;
            float p0=fmaxf(fmaxf(s0,0.f),fmaxf(s1,0.f));
            float p1=fmaxf(fmaxf(s2,0.f),fmaxf(s3,0.f));
            float q0=fmaxf(p0, __shfl_down_sync(0xffffffffu,p0,1));
            float q1=fmaxf(p1, __shfl_down_sync(0xffffffffu,p1,1));
            if(!(lane&1) && lane<28){
                int wo=wc>>1;
                out[((size_t)(b*16+oc)*96+pho0+2*pp+0)*14+wo]=q0;
                out[((size_t)(b*16+oc)*96+pho0+2*pp+1)*14+wo]=q1;
            }
        }
    }
}

__global__ __launch_bounds__(256) void conv3_k(const float* __restrict__ in,
        const float* __restrict__ cw, const float* __restrict__ cb, float* __restrict__ out){
    __shared__ float4 xin[4*26*16];
    __shared__ float4 w_s[576];
    __shared__ float  b_s[16];
    int b = blockIdx.x>>2, pho0 = (blockIdx.x&3)*8;
    int tid = threadIdx.x, lane = tid&31, warp = tid>>5;
    for(int f=tid; f<4*26*16; f+=256){
        int icg=f/(26*16), rr=(f/16)%26, cc=f%16;
        int gr=pho0*3-1+rr, gc=cc-1;
        float4 v={0,0,0,0};
        if(gr>=0 && gr<96 && gc>=0 && gc<14){
            const float* p = in + ((size_t)(b*16+icg*4)*96+gr)*14+gc;
            v.x=p[0]; v.y=p[96*14]; v.z=p[2*96*14]; v.w=p[3*96*14];
        }
        xin[f]=v;
    }
    for(int f=tid; f<576; f+=256){
        int oc=f/36, icg=(f/9)%4, k=f%9;
        float4 v;
        v.x=cw[(oc*16+icg*4+0)*9+k]; v.y=cw[(oc*16+icg*4+1)*9+k];
        v.z=cw[(oc*16+icg*4+2)*9+k]; v.w=cw[(oc*16+icg*4+3)*9+k];
        w_s[f]=v;
    }
    if(tid<16) b_s[tid]=cb[tid];
    __syncthreads();
    int half = lane>>4;
    int hw = warp*2 + half;
    int wc = min(lane&15, 13);
    #pragma unroll 1
    for(int it=hw; it<64; it+=16){
        int pair = it>>3, ph = it&7;
        int oc0 = pair, oc1 = pair+8;
        float4 acc[2][3];
        #pragma unroll
        for(int o=0;o<2;o++)
            #pragma unroll
            for(int r=0;r<3;r++) acc[o][r]=make_float4(0,0,0,0);
        #pragma unroll
        for(int icg=0;icg<4;icg++){
            #pragma unroll
            for(int kw=0;kw<3;kw++){
                float4 X[5];
                #pragma unroll
                for(int r=0;r<5;r++) X[r]=xin[(icg*26+3*ph+r)*16+wc+kw];
                #pragma unroll
                for(int kh=0;kh<3;kh++){
                    float4 w0=w_s[(oc0*4+icg)*9+kh*3+kw];
                    float4 w1=w_s[(oc1*4+icg)*9+kh*3+kw];
                    ffma4p(acc[0][0],X[kh],w0);
                    ffma4p(acc[0][1],X[kh+1],w0);
                    ffma4p(acc[0][2],X[kh+2],w0);
                    ffma4p(acc[1][0],X[kh],w1);
                    ffma4p(acc[1][1],X[kh+1],w1);
                    ffma4p(acc[1][2],X[kh+2],w1);
                }
            }
        }
        #pragma unroll
        for(int o=0;o<2;o++){
            int oc = o ? oc1 : oc0;
            float bv = b_s[oc];
            float s0=fmaxf(hsum4(acc[o][0])+bv,0.f);
            float s1=fmaxf(hsum4(acc[o][1])+bv,0.f);
            float s2=fmaxf(hsum4(acc[o][2])+bv,0.f);
            float v=fmaxf(fmaxf(s0,s1),s2);
            float ov=fmaxf(v, __shfl_down_sync(0xffffffffu,v,1));
            if(!(lane&1) && (lane&15)<14)
                out[((size_t)(b*16+oc)*32+pho0+ph)*7+(wc>>1)]=ov;
        }
    }
}

__global__ __launch_bounds__(256) void conv4_k(const float* __restrict__ in,
        const float* __restrict__ cw, const float* __restrict__ cb, float* __restrict__ out){
    __shared__ float4 xin[4*34*9];
    __shared__ float4 w_s[1152];
    __shared__ float  b_s[32];
    int b = blockIdx.x;
    int tid = threadIdx.x, lane = tid&31, warp = tid>>5;
    for(int f=tid; f<4*34*9; f+=256){
        int icg=f/(34*9), rr=(f/9)%34, cc=f%9;
        int gr=rr-1, gc=cc-1;
        float4 v={0,0,0,0};
        if(gr>=0 && gr<32 && gc>=0 && gc<7){
            const float* p = in + ((size_t)(b*16+icg*4)*32+gr)*7+gc;
            v.x=p[0]; v.y=p[32*7]; v.z=p[2*32*7]; v.w=p[3*32*7];
        }
        xin[f]=v;
    }
    for(int f=tid; f<1152; f+=256){
        int oc=f/36, icg=(f/9)%4, k=f%9;
        float4 v;
        v.x=cw[(oc*16+icg*4+0)*9+k]; v.y=cw[(oc*16+icg*4+1)*9+k];
        v.z=cw[(oc*16+icg*4+2)*9+k]; v.w=cw[(oc*16+icg*4+3)*9+k];
        w_s[f]=v;
    }
    if(tid<32) b_s[tid]=cb[tid];
    __syncthreads();
    int quarter = lane>>3;
    int qw = warp*4 + quarter;
    int wc = min(lane&7, 6);
    #pragma unroll 1
    for(int it=qw; it<128; it+=32){
        int pair = it>>3, hq = it&7;
        int oc0 = pair, oc1 = pair+16;
        float4 ac[2][4];
        #pragma unroll
        for(int o=0;o<2;o++)
            #pragma unroll
            for(int r=0;r<4;r++) ac[o][r]=make_float4(0,0,0,0);
        #pragma unroll
        for(int icg=0;icg<4;icg++){
            #pragma unroll
            for(int kw=0;kw<3;kw++){
                float4 X[6];
                #pragma unroll
                for(int r=0;r<6;r++) X[r]=xin[(icg*34+4*hq+r)*9+wc+kw];
                #pragma unroll
                for(int kh=0;kh<3;kh++){
                    float4 w0=w_s[(oc0*4+icg)*9+kh*3+kw];
                    float4 w1=w_s[(oc1*4+icg)*9+kh*3+kw];
                    #pragma unroll
                    for(int r=0;r<4;r++) ffma4p(ac[0][r],X[r+kh],w0);
                    #pragma unroll
                    for(int r=0;r<4;r++) ffma4p(ac[1][r],X[r+kh],w1);
                }
            }
        }
        #pragma unroll
        for(int o=0;o<2;o++){
            int oc = o ? oc1 : oc0;
            float bv = b_s[oc];
            #pragma unroll
            for(int r=0;r<4;r++){
                float s=fmaxf(hsum4(ac[o][r])+bv,0.f);
                if((lane&7)<7)
                    out[((size_t)b*32+hq*4+r)*224+wc*32+oc]=s;
            }
        }
    }
}

// =====================  merged prep kernel  =====================
#define SEG0 100352
#define SEG1 (SEG0+100352)
#define SEG2 (SEG1+114688)
#define SEG3 (SEG2+131072)
#define SEG4 (SEG3+896)
#define SEG5 (SEG4+1024)
__global__ void prep_k(const float* __restrict__ lstmWih, const float* __restrict__ lstmWhh,
        const float* __restrict__ decWih, const float* __restrict__ decWhh,
        const float* __restrict__ lstmbih, const float* __restrict__ lstmbhh,
        const float* __restrict__ decbih, const float* __restrict__ decbhh){
    int idx = blockIdx.x*blockDim.x+threadIdx.x;
    if(idx >= SEG5) return;
    if(idx < SEG3){
        const float* W; uint32_t *Wh, *Wl;
        int base, kp2, kstride, gatesize;
        if(idx < SEG0){ W=lstmWih; Wh=g_WihH; Wl=g_WihL; base=0;    kp2=112; kstride=112; gatesize=224; }
        else if(idx < SEG1){ W=lstmWhh; Wh=g_WhhH; Wl=g_WhhL; base=SEG0; kp2=112; kstride=112; gatesize=224; }
        else if(idx < SEG2){ W=decWih;  Wh=g_WdH;  Wl=g_WdL;  base=SEG1; kp2=112; kstride=240; gatesize=256; }
        else { W=decWhh; Wh=g_WdH+112; Wl=g_WdL+112; base=SEG2; kp2=128; kstride=240; gatesize=256; }
        int li = idx - base;
        int kp = li%kp2, np = li/kp2;
        int Ksrc = kp2*2;
        int j=np>>2, gg=np&3;
        int srow = gg*gatesize+j;
        float x = W[(size_t)srow*Ksrc+2*kp], y = W[(size_t)srow*Ksrc+2*kp+1];
        uint32_t h,l; splitpair(x,y,h,l);
        Wh[(size_t)np*kstride+kp]=h; Wl[(size_t)np*kstride+kp]=l;
    } else if(idx < SEG4){
        int np = idx - SEG3;
        int j=np>>2, gg=np&3, s=gg*224+j;
        g_bsE[np] = lstmbih[s]+lstmbhh[s];
    } else {
        int np = idx - SEG4;
        int j=np>>2, gg=np&3, s=gg*256+j;
        g_bsD[np] = decbih[s]+decbhh[s];
    }
}

__global__ void split_a_k(const float* __restrict__ A, uint32_t* __restrict__ Ahi,
                          uint32_t* __restrict__ Alo, int total){
    int idx = blockIdx.x*blockDim.x+threadIdx.x;
    if(idx>=total) return;
    uint32_t h,l; splitpair(A[2*idx], A[2*idx+1], h, l);
    Ahi[idx]=h; Alo[idx]=l;
}
__global__ void init_enc_k(const float* __restrict__ h0, const float* __restrict__ c0){
    int idx = blockIdx.x*blockDim.x+threadIdx.x;
    if(idx < BSZ*AD) g_c[idx] = __ldg(c0 + idx%AD);
    if(idx < BSZ*112){
        int k = idx%112;
        uint32_t h,l; splitpair(__ldg(h0+2*k), __ldg(h0+2*k+1), h, l);
        g_Hh[idx]=h; g_Hl[idx]=l;
    }
}
__global__ void init_dec_k(){
    int idx = blockIdx.x*blockDim.x+threadIdx.x;
    if(idx>=BSZ*HID) return;
    g_dh[idx]=0.f; g_dc[idx]=0.f;
    int k = idx&255;
    if(k<128){ g_Ch[(idx>>8)*240+112+k]=0u; g_Cl[(idx>>8)*240+112+k]=0u; }
}
__global__ void enc_score_k(const float* __restrict__ att_w){
    int gl = blockIdx.x*blockDim.x+threadIdx.x;
    int row = gl>>5, lane = gl&31;
    if(row>=BSZ*TT) return;
    const float* r = g_y8 + (size_t)row*AD;
    const float* we = att_w + HID;
    float s=0.f;
    for(int k=lane;k<AD;k+=32) s += r[k]*__ldg(we+k);
    #pragma unroll
    for(int o=16;o>0;o>>=1) s += __shfl_xor_sync(0xffffffffu,s,o);
    if(lane==0) g_escore[row]=s;
}

// =====================  MMA cores  =====================
#define MMA(c, a, b) asm volatile( \
    "mma.sync.aligned.m16n8k16.row.col.f32.bf16.bf16.f32 " \
    "{%0,%1,%2,%3},{%4,%5,%6,%7},{%8,%9},{%0,%1,%2,%3};" \
    : "+f"(c[0]),"+f"(c[1]),"+f"(c[2]),"+f"(c[3]) \
    : "r"(a[0]),"r"(a[1]),"r"(a[2]),"r"(a[3]),"r"(b[0]),"r"(b[1]))

// ---- 64x64 core for gemm_x (8 warps, warp grid 2x4, 32x16 per warp) ----
__device__ __forceinline__ void mma_block64(const uint32_t* __restrict__ Ah,
        const uint32_t* __restrict__ Al, const uint32_t* __restrict__ Bh,
        const uint32_t* __restrict__ Bl,
        float (&acc)[2][2][4], int wm, int wn, int g, int tg){
    #pragma unroll
    for(int kk=0;kk<2;kk++){
        uint32_t aH[2][4], aL[2][4], bH[2][2], bL[2][2];
        int kp = kk*8+tg;
        #pragma unroll
        for(int mi=0;mi<2;mi++){
            int r0 = wm*32+mi*16+g;
            aH[mi][0]=Ah[r0*17+kp];   aH[mi][1]=Ah[(r0+8)*17+kp];
            aH[mi][2]=Ah[r0*17+kp+4]; aH[mi][3]=Ah[(r0+8)*17+kp+4];
            aL[mi][0]=Al[r0*17+kp];   aL[mi][1]=Al[(r0+8)*17+kp];
            aL[mi][2]=Al[r0*17+kp+4]; aL[mi][3]=Al[(r0+8)*17+kp+4];
        }
        #pragma unroll
        for(int ni=0;ni<2;ni++){
            int c0 = wn*16+ni*8+g;
            bH[ni][0]=Bh[c0*17+kp]; bH[ni][1]=Bh[c0*17+kp+4];
            bL[ni][0]=Bl[c0*17+kp]; bL[ni][1]=Bl[c0*17+kp+4];
        }
        #pragma unroll
        for(int mi=0;mi<2;mi++)
            #pragma unroll
            for(int ni=0;ni<2;ni++){
                MMA(acc[mi][ni], aH[mi], bH[ni]);
                MMA(acc[mi][ni], aL[mi], bH[ni]);
                MMA(acc[mi][ni], aH[mi], bL[ni]);
            }
    }
}

#define BUFSZ64 (4*64*17)

template<int NCHUNK>
__device__ __forceinline__ void gemm_pipe64(
        const uint32_t* __restrict__ AsrcH, const uint32_t* __restrict__ AsrcL, int astr,
        const uint32_t* __restrict__ BsrcH, const uint32_t* __restrict__ BsrcL, int bstr,
        uint32_t* P, float (&acc)[2][2][4], int tid, int wm, int wn, int g, int tg){
    int lr = tid>>2, lkp = (tid&3)*4;
    const uint32_t* pah = AsrcH + (size_t)lr*astr + lkp;
    const uint32_t* pal = AsrcL + (size_t)lr*astr + lkp;
    const uint32_t* pbh = BsrcH + (size_t)lr*bstr + lkp;
    const uint32_t* pbl = BsrcL + (size_t)lr*bstr + lkp;
    uint4 ra = *(const uint4*)pah;
    uint4 rb = *(const uint4*)pal;
    uint4 rc = *(const uint4*)pbh;
    uint4 rd = *(const uint4*)pbl;
    int o = lr*17 + lkp;
    #pragma unroll
    for(int c=0;c<NCHUNK;c++){
        uint32_t* buf = P + (c&1)*BUFSZ64;
        buf[o+0]=ra.x; buf[o+1]=ra.y; buf[o+2]=ra.z; buf[o+3]=ra.w;
        buf[1088+o+0]=rb.x; buf[1088+o+1]=rb.y; buf[1088+o+2]=rb.z; buf[1088+o+3]=rb.w;
        buf[2176+o+0]=rc.x; buf[2176+o+1]=rc.y; buf[2176+o+2]=rc.z; buf[2176+o+3]=rc.w;
        buf[3264+o+0]=rd.x; buf[3264+o+1]=rd.y; buf[3264+o+2]=rd.z; buf[3264+o+3]=rd.w;
        __syncthreads();
        if(c+1<NCHUNK){
            ra = *(const uint4*)(pah + (c+1)*16);
            rb = *(const uint4*)(pal + (c+1)*16);
            rc = *(const uint4*)(pbh + (c+1)*16);
            rd = *(const uint4*)(pbl + (c+1)*16);
        }
        mma_block64(buf, buf+1088, buf+2176, buf+3264, acc, wm, wn, g, tg);
    }
}

// ---- 64x32 core for the scans (8 warps, warp grid 2x4, 32x8 per warp) ----
// buffer layout (u32): Ah 64*17 | Al 64*17 | Bh 32*17 | Bl 32*17 = 3264
#define BUFSZ32 3264

__device__ __forceinline__ void mma_block32(const uint32_t* __restrict__ Ah,
        const uint32_t* __restrict__ Al, const uint32_t* __restrict__ Bh,
        const uint32_t* __restrict__ Bl,
        float (&acc)[2][4], int wm, int wn, int g, int tg){
    #pragma unroll
    for(int kk=0;kk<2;kk++){
        uint32_t aH[2][4], aL[2][4], bH[2], bL[2];
        int kp = kk*8+tg;
        #pragma unroll
        for(int mi=0;mi<2;mi++){
            int r0 = wm*32+mi*16+g;
            aH[mi][0]=Ah[r0*17+kp];   aH[mi][1]=Ah[(r0+8)*17+kp];
            aH[mi][2]=Ah[r0*17+kp+4]; aH[mi][3]=Ah[(r0+8)*17+kp+4];
            aL[mi][0]=Al[r0*17+kp];   aL[mi][1]=Al[(r0+8)*17+kp];
            aL[mi][2]=Al[r0*17+kp+4]; aL[mi][3]=Al[(r0+8)*17+kp+4];
        }
        {
            int c0 = wn*8+g;
            bH[0]=Bh[c0*17+kp]; bH[1]=Bh[c0*17+kp+4];
            bL[0]=Bl[c0*17+kp]; bL[1]=Bl[c0*17+kp+4];
        }
        #pragma unroll
        for(int mi=0;mi<2;mi++){
            MMA(acc[mi], aH[mi], bH);
            MMA(acc[mi], aL[mi], bH);
            MMA(acc[mi], aH[mi], bL);
        }
    }
}

template<int NCHUNK, bool PDL>
__device__ __forceinline__ void gemm_pipe32(
        const uint32_t* __restrict__ AsrcH, const uint32_t* __restrict__ AsrcL, int astr,
        const uint32_t* __restrict__ BsrcH, const uint32_t* __restrict__ BsrcL, int bstr,
        uint32_t* P, float (&acc)[2][4], int tid, int wm, int wn, int g, int tg){
    int lrA = tid>>2, lkpA = (tid&3)*4;
    int lrB = tid>>3, lkpB = (tid&7)*2;
    const uint32_t* pah = AsrcH + (size_t)lrA*astr + lkpA;
    const uint32_t* pal = AsrcL + (size_t)lrA*astr + lkpA;
    const uint32_t* pbh = BsrcH + (size_t)lrB*bstr + lkpB;
    const uint32_t* pbl = BsrcL + (size_t)lrB*bstr + lkpB;
    uint2 rc = *(const uint2*)pbh;        // weights: step-invariant, safe pre-sync
    uint2 rd = *(const uint2*)pbl;
    if(PDL) cudaGridDependencySynchronize();
    uint4 ra = *(const uint4*)pah;        // activations: depend on predecessor
    uint4 rb = *(const uint4*)pal;
    int oA = lrA*17 + lkpA;
    int oB = lrB*17 + lkpB;
    #pragma unroll
    for(int c=0;c<NCHUNK;c++){
        uint32_t* buf = P + (c&1)*BUFSZ32;
        buf[oA+0]=ra.x; buf[oA+1]=ra.y; buf[oA+2]=ra.z; buf[oA+3]=ra.w;
        buf[1088+oA+0]=rb.x; buf[1088+oA+1]=rb.y; buf[1088+oA+2]=rb.z; buf[1088+oA+3]=rb.w;
        buf[2176+oB+0]=rc.x; buf[2176+oB+1]=rc.y;
        buf[2720+oB+0]=rd.x; buf[2720+oB+1]=rd.y;
        __syncthreads();
        if(c+1<NCHUNK){
            ra = *(const uint4*)(pah + (c+1)*16);
            rb = *(const uint4*)(pal + (c+1)*16);
            rc = *(const uint2*)(pbh + (c+1)*16);
            rd = *(const uint2*)(pbl + (c+1)*16);
        }
        mma_block32(buf, buf+1088, buf+2176, buf+2720, acc, wm, wn, g, tg);
    }
}

// =====================  xW GEMM (one-shot, 64x64)  =====================
__global__ __launch_bounds__(256) void gemm_x(){
    __shared__ uint32_t P[2*BUFSZ64];
    int tid=threadIdx.x;
    int m0=blockIdx.y*64, n0=blockIdx.x*64;
    int warp=tid>>5, lane=tid&31;
    int wm=warp>>2, wn=warp&3, g=lane>>2, tg=lane&3;
    float acc[2][2][4];
    #pragma unroll
    for(int mi=0;mi<2;mi++)
        #pragma unroll
        for(int ni=0;ni<2;ni++)
            #pragma unroll
            for(int r=0;r<4;r++) acc[mi][ni][r]=0.f;
    gemm_pipe64<7>(g_Y5h + (size_t)m0*112, g_Y5l + (size_t)m0*112, 112,
                 g_WihH + (size_t)n0*112, g_WihL + (size_t)n0*112, 112,
                 P, acc, tid, wm, wn, g, tg);
    #pragma unroll
    for(int mi=0;mi<2;mi++){
        int row = m0+wm*32+mi*16+g;
        #pragma unroll
        for(int ni=0;ni<2;ni++){
            int col = n0+wn*16+ni*8+tg*2;
            float* p0 = g_xW + (size_t)row*896 + col;
            float* p1 = g_xW + (size_t)(row+8)*896 + col;
            p0[0]=acc[mi][ni][0]; p0[1]=acc[mi][ni][1];
            p1[0]=acc[mi][ni][2]; p1[1]=acc[mi][ni][3];
        }
    }
}

// =====================  encoder step (64x32 tiles, PDL)  =====================
__global__ __launch_bounds__(256) void enc_step(int t){
    __shared__ uint32_t P[2*BUFSZ32];
    float* cs = (float*)(P + BUFSZ32);   // last mma (chunk 6) reads buffer 0 -> cs aliases buffer 1
    int tid=threadIdx.x;
    int m0=blockIdx.y*64, n0=blockIdx.x*32;
    int warp=tid>>5, lane=tid&31;
    int wm=warp>>2, wn=warp&3, g=lane>>2, tg=lane&3;
    const uint32_t* srcH = g_Hh + (size_t)(t&1)*(BSZ*112);
    const uint32_t* srcL = g_Hl + (size_t)(t&1)*(BSZ*112);
    uint32_t* dstH = g_Hh + (size_t)((t+1)&1)*(BSZ*112);
    uint32_t* dstL = g_Hl + (size_t)((t+1)&1)*(BSZ*112);
    float acc[2][4];
    #pragma unroll
    for(int mi=0;mi<2;mi++)
        #pragma unroll
        for(int r=0;r<4;r++) acc[mi][r]=0.f;
    gemm_pipe32<7,true>(srcH + (size_t)m0*112, srcL + (size_t)m0*112, 112,
                 g_WhhH + (size_t)n0*112, g_WhhL + (size_t)n0*112, 112,
                 P, acc, tid, wm, wn, g, tg);
    // stage acc tile (64 x 32, stride 34)
    #pragma unroll
    for(int mi=0;mi<2;mi++){
        int r0 = wm*32+mi*16+g;
        int c0c = wn*8+tg*2;
        cs[r0*34+c0c]=acc[mi][0];     cs[r0*34+c0c+1]=acc[mi][1];
        cs[(r0+8)*34+c0c]=acc[mi][2]; cs[(r0+8)*34+c0c+1]=acc[mi][3];
    }
    __syncthreads();
    {
        int m = tid>>2, jp = tid&3;
        int b = m0+m;
        const float* xw = g_xW + ((size_t)b*TT + t)*896 + n0 + 8*jp;
        float4 x0 = *(const float4*)xw;
        float4 x1 = *(const float4*)(xw+4);
        float4 s0 = *(const float4*)(g_bsE + n0 + 8*jp);
        float4 s1 = *(const float4*)(g_bsE + n0 + 8*jp + 4);
        const float* cp = cs + m*34 + 8*jp;
        float gi0=cp[0]+x0.x+s0.x, gf0=cp[1]+x0.y+s0.y, gg0=cp[2]+x0.z+s0.z, go0=cp[3]+x0.w+s0.w;
        float gi1=cp[4]+x1.x+s1.x, gf1=cp[5]+x1.y+s1.y, gg1=cp[6]+x1.z+s1.z, go1=cp[7]+x1.w+s1.w;
        int j0 = (n0>>2) + 2*jp;
        float c0v = g_c[(size_t)b*AD + j0];
        float c1v = g_c[(size_t)b*AD + j0 + 1];
        float cc0 = sigm(gf0)*c0v + sigm(gi0)*tanhf(gg0);
        float cc1 = sigm(gf1)*c1v + sigm(gi1)*tanhf(gg1);
        float h0v = sigm(go0)*tanhf(cc0);
        float h1v = sigm(go1)*tanhf(cc1);
        g_c[(size_t)b*AD + j0]   = cc0;
        g_c[(size_t)b*AD + j0+1] = cc1;
        float* yp = g_y8 + ((size_t)b*TT + t)*AD + j0;
        yp[0]=h0v; yp[1]=h1v;
        uint32_t hh,ll; splitpair(h0v,h1v,hh,ll);
        dstH[(size_t)b*112 + (n0>>3) + jp] = hh;
        dstL[(size_t)b*112 + (n0>>3) + jp] = ll;
    }
}

// =====================  decoder step GEMM+cell (64x32 tiles, PDL)  =====================
__global__ __launch_bounds__(256) void dec_step(int s){
    __shared__ uint32_t P[2*BUFSZ32];
    float* cs = (float*)(P + BUFSZ32);   // last mma (chunk 14) reads buffer 0 -> cs aliases buffer 1
    int tid=threadIdx.x;
    int m0=blockIdx.y*64, n0=blockIdx.x*32;
    int warp=tid>>5, lane=tid&31;
    int wm=warp>>2, wn=warp&3, g=lane>>2, tg=lane&3;
    const uint32_t* srcH = g_Ch + (size_t)(s&1)*(BSZ*240);
    const uint32_t* srcL = g_Cl + (size_t)(s&1)*(BSZ*240);
    uint32_t* dstH = g_Ch + (size_t)((s+1)&1)*(BSZ*240);
    uint32_t* dstL = g_Cl + (size_t)((s+1)&1)*(BSZ*240);
    float acc[2][4];
    #pragma unroll
    for(int mi=0;mi<2;mi++)
        #pragma unroll
        for(int r=0;r<4;r++) acc[mi][r]=0.f;
    gemm_pipe32<15,true>(srcH + (size_t)m0*240, srcL + (size_t)m0*240, 240,
                  g_WdH + (size_t)n0*240, g_WdL + (size_t)n0*240, 240,
                  P, acc, tid, wm, wn, g, tg);
    #pragma unroll
    for(int mi=0;mi<2;mi++){
        int r0 = wm*32+mi*16+g;
        int c0c = wn*8+tg*2;
        cs[r0*34+c0c]=acc[mi][0];     cs[r0*34+c0c+1]=acc[mi][1];
        cs[(r0+8)*34+c0c]=acc[mi][2]; cs[(r0+8)*34+c0c+1]=acc[mi][3];
    }
    __syncthreads();
    float* dhh = g_dhh[s];
    {
        int m = tid>>2, jp = tid&3;
        int b = m0+m;
        float4 s0 = *(const float4*)(g_bsD + n0 + 8*jp);
        float4 s1 = *(const float4*)(g_bsD + n0 + 8*jp + 4);
        const float* cp = cs + m*34 + 8*jp;
        float gi0=cp[0]+s0.x, gf0=cp[1]+s0.y, gg0=cp[2]+s0.z, go0=cp[3]+s0.w;
        float gi1=cp[4]+s1.x, gf1=cp[5]+s1.y, gg1=cp[6]+s1.z, go1=cp[7]+s1.w;
        int j0 = (n0>>2) + 2*jp;
        float c0v = g_dc[(size_t)b*HID + j0];
        float c1v = g_dc[(size_t)b*HID + j0 + 1];
        float cc0 = sigm(gf0)*c0v + sigm(gi0)*tanhf(gg0);
        float cc1 = sigm(gf1)*c1v + sigm(gi1)*tanhf(gg1);
        float h0v = sigm(go0)*tanhf(cc0);
        float h1v = sigm(go1)*tanhf(cc1);
        g_dc[(size_t)b*HID + j0]   = cc0;
        g_dc[(size_t)b*HID + j0+1] = cc1;
        g_dh[(size_t)b*HID + j0]   = h0v;
        g_dh[(size_t)b*HID + j0+1] = h1v;
        dhh[(size_t)b*HID + j0]    = h0v;
        dhh[(size_t)b*HID + j0+1]  = h1v;
        uint32_t hh,ll; splitpair(h0v,h1v,hh,ll);
        dstH[(size_t)b*240 + 112 + (n0>>3) + jp] = hh;
        dstL[(size_t)b*240 + 112 + (n0>>3) + jp] = ll;
    }
}

// =====================  attention (PDL; out-proj deferred)  =====================
__global__ __launch_bounds__(256) void attn_k(const float* __restrict__ attw,
        const float* __restrict__ attb, int s){
    cudaGridDependencySynchronize();
    int b = blockIdx.x, tid = threadIdx.x;
    __shared__ float dh_s[256];
    __shared__ float red[256];
    __shared__ float sc[TT];
    __shared__ float ctx_s[AD];
    dh_s[tid] = g_dh[(size_t)b*HID + tid];
    __syncthreads();

    red[tid] = dh_s[tid]*__ldg(attw+tid);
    __syncthreads();
    #pragma unroll
    for(int r=128;r>0;r>>=1){ if(tid<r) red[tid]+=red[tid+r]; __syncthreads(); }
    float hw = red[0] + __ldg(attb);
    if(tid < 32){
        float x = g_escore[b*TT + tid] + hw;
        float mx = x;
        #pragma unroll
        for(int o=16;o>0;o>>=1) mx = fmaxf(mx,__shfl_xor_sync(0xffffffffu,mx,o));
        float e = __expf(x-mx), sm = e;
        #pragma unroll
        for(int o=16;o>0;o>>=1) sm += __shfl_xor_sync(0xffffffffu,sm,o);
        sc[tid] = __fdividef(e, sm);
    }
    __syncthreads();
    if(tid < AD){
        const float* y = g_y8 + (size_t)b*TT*AD + tid;
        float acc=0.f;
        #pragma unroll
        for(int t=0;t<TT;t++) acc = fmaf(sc[t], y[t*AD], acc);
        ctx_s[tid]=acc;
    }
    __syncthreads();
    if(tid < 112){
        uint32_t hh,ll; splitpair(ctx_s[2*tid], ctx_s[2*tid+1], hh, ll);
        g_Ch[(size_t)(s&1)*(BSZ*240) + (size_t)b*240 + tid] = hh;
        g_Cl[(size_t)(s&1)*(BSZ*240) + (size_t)b*240 + tid] = ll;
    }
}

// =====================  batched output projection (all 25 steps)  =====================
__global__ __launch_bounds__(256) void out_all_k(const float* __restrict__ outw,
        const float* __restrict__ outb, float* __restrict__ out){
    int gw = blockIdx.x*8 + (threadIdx.x>>5);
    int lane = threadIdx.x & 31;
    if(gw >= OUT_LEN*BSZ) return;
    int s = gw / BSZ, b = gw % BSZ;
    const float* dh = g_dhh[s] + (size_t)b*HID;
    float dv[8];
    #pragma unroll
    for(int q=0;q<8;q++) dv[q] = dh[lane+32*q];
    #pragma unroll 1
    for(int v=0; v<VOCAB; v++){
        const float* wp = outw + (size_t)v*HID;
        float sum = 0.f;
        #pragma unroll
        for(int q=0;q<8;q++) sum = fmaf(dv[q], __ldg(wp+lane+32*q), sum);
        #pragma unroll
        for(int o=16;o>0;o>>=1) sum += __shfl_xor_sync(0xffffffffu,sum,o);
        if(lane==0)
            out[(size_t)b*VOCAB*OUT_LEN + v*OUT_LEN + s] = sum + __ldg(outb+v);
    }
}

// =====================  launch  =====================
extern "C" void kernel_launch(void* const* d_in, const int* in_sizes, int n_in,
                              void* d_out, int out_size){
    const float* x       = (const float*)d_in[0];
    const float* c1w     = (const float*)d_in[1];
    const float* c1b     = (const float*)d_in[2];
    const float* c2w     = (const float*)d_in[3];
    const float* c2b     = (const float*)d_in[4];
    const float* c3w     = (const float*)d_in[5];
    const float* c3b     = (const float*)d_in[6];
    const float* c4w     = (const float*)d_in[7];
    const float* c4b     = (const float*)d_in[8];
    const float* h0      = (const float*)d_in[9];
    const float* c0      = (const float*)d_in[10];
    const float* lstmWih = (const float*)d_in[11];
    const float* lstmWhh = (const float*)d_in[12];
    const float* lstmbih = (const float*)d_in[13];
    const float* lstmbhh = (const float*)d_in[14];
    const float* attw    = (const float*)d_in[15];
    const float* attb    = (const float*)d_in[16];
    const float* decWih  = (const float*)d_in[17];
    const float* decWhh  = (const float*)d_in[18];
    const float* decbih  = (const float*)d_in[19];
    const float* decbhh  = (const float*)d_in[20];
    const float* outw    = (const float*)d_in[21];
    const float* outb    = (const float*)d_in[22];
    float* out = (float*)d_out;

    float *y1,*y2,*y3,*y5;
    uint32_t *Y5h,*Y5l;
    cudaGetSymbolAddress((void**)&y1,  g_y1);
    cudaGetSymbolAddress((void**)&y2,  g_y2);
    cudaGetSymbolAddress((void**)&y3,  g_y3);
    cudaGetSymbolAddress((void**)&y5,  g_y5);
    cudaGetSymbolAddress((void**)&Y5h, g_Y5h);
    cudaGetSymbolAddress((void**)&Y5l, g_Y5l);

    // merged weight prep (1 launch)
    prep_k<<<(SEG5+255)/256,256>>>(lstmWih, lstmWhh, decWih, decWhh,
                                   lstmbih, lstmbhh, decbih, decbhh);

    // conv stack
    conv1_k<<<BSZ*6,256>>>(x,  c1w, c1b, y1);
    conv2_k<<<BSZ*6,256>>>(y1, c2w, c2b, y2);
    conv3_k<<<BSZ*4,256>>>(y2, c3w, c3b, y3);
    conv4_k<<<BSZ,  256>>>(y3, c4w, c4b, y5);

    // split y5 then xW GEMM
    split_a_k<<<(BSZ*TT*112+255)/256,256>>>(y5, Y5h, Y5l, BSZ*TT*112);
    gemm_x<<<dim3(14,512),256>>>();

    // encoder scan (PDL launches, 64x32 tiles -> 448 blocks)
    init_enc_k<<<(BSZ*AD+255)/256,256>>>(h0, c0);
    cudaLaunchAttribute pdlAttr[1];
    pdlAttr[0].id = cudaLaunchAttributeProgrammaticStreamSerialization;
    pdlAttr[0].val.programmaticStreamSerializationAllowed = 1;
    for(int t=0;t<TT;t++){
        cudaLaunchConfig_t cfg = {};
        cfg.gridDim = dim3(28,16);
        cfg.blockDim = dim3(256);
        cfg.attrs = pdlAttr;
        cfg.numAttrs = 1;
        cudaLaunchKernelEx(&cfg, enc_step, t);
    }

    // attention precompute + decoder init
    enc_score_k<<<(BSZ*TT*32+255)/256,256>>>(attw);
    init_dec_k<<<(BSZ*HID+255)/256,256>>>();

    // decoder scan (PDL launches, 64x32 tiles -> 512 blocks)
    for(int s=0;s<OUT_LEN;s++){
        {
            cudaLaunchConfig_t cfg = {};
            cfg.gridDim = dim3(BSZ);
            cfg.blockDim = dim3(256);
            cfg.attrs = pdlAttr;
            cfg.numAttrs = 1;
            cudaLaunchKernelEx(&cfg, attn_k, attw, attb, s);
        }
        {
            cudaLaunchConfig_t cfg = {};
            cfg.gridDim = dim3(32,16);
            cfg.blockDim = dim3(256);
            cfg.attrs = pdlAttr;
            cfg.numAttrs = 1;
            cudaLaunchKernelEx(&cfg, dec_step, s);
        }
    }

    // batched output projection for all steps
    out_all_k<<<(OUT_LEN*BSZ+7)/8,256>>>(outw, outb, out);
}

// round 16
// speedup vs baseline: 1.4342x; 1.4342x over previous
#include <cuda_runtime.h>
#include <cuda_bf16.h>
#include <cstdint>

#define BSZ  1024
#define TT   32
#define AD   224
#define HID  256
#define VOCAB 29
#define OUT_LEN 25

// ---------------- scratch (device globals) ----------------
__device__ float g_y1[BSZ*4*192*28];
__device__ float g_y2[BSZ*16*96*14];
__device__ float g_y3[BSZ*16*32*7];
__device__ float g_y5[BSZ*TT*AD];
__device__ __align__(16) float g_xW[BSZ*TT*896];
__device__ __align__(16) float g_y8[BSZ*TT*AD];
__device__ float g_escore[BSZ*TT];
__device__ float g_c [BSZ*AD];
__device__ float g_dc[BSZ*HID];
__device__ __align__(16) float g_ctxW[BSZ*1024];          // ctx@decWih^T + bsD (step-invariant)
__device__ __align__(16) float g_dhh[OUT_LEN][BSZ*HID];   // dh history for deferred out-proj
// pre-split activations (bf16 hi/lo pairs packed as u32)
__device__ __align__(16) uint32_t g_Y5h[BSZ*TT*112], g_Y5l[BSZ*TT*112];
__device__ __align__(16) uint32_t g_Hh[2*BSZ*112],   g_Hl[2*BSZ*112];
__device__ __align__(16) uint32_t g_DhH[2][BSZ*128], g_DhL[2][BSZ*128];
__device__ __align__(16) uint32_t g_CtxH[BSZ*112],   g_CtxL[BSZ*112];
// pre-split weights, gate-interleaved rows
__device__ __align__(16) uint32_t g_WihH[896*112],  g_WihL[896*112];
__device__ __align__(16) uint32_t g_WhhH[896*112],  g_WhhL[896*112];
__device__ __align__(16) uint32_t g_WdihH[1024*112], g_WdihL[1024*112];
__device__ __align__(16) uint32_t g_WdhhH[1024*128], g_WdhhL[1024*128];
__device__ __align__(16) float g_bsE[896], g_bsD[1024];

__device__ __forceinline__ float sigm(float x){
    return __fdividef(1.0f, 1.0f + __expf(-x));
}
__device__ __forceinline__ void ffma4p(float4& a, const float4& x, const float4& w){
    unsigned long long* ap = reinterpret_cast<unsigned long long*>(&a);
    const unsigned long long* xp = reinterpret_cast<const unsigned long long*>(&x);
    const unsigned long long* wp = reinterpret_cast<const unsigned long long*>(&w);
    asm("fma.rn.f32x2 %0, %1, %2, %0;" : "+l"(ap[0]) : "l"(xp[0]), "l"(wp[0]));
    asm("fma.rn.f32x2 %0, %1, %2, %0;" : "+l"(ap[1]) : "l"(xp[1]), "l"(wp[1]));
}
__device__ __forceinline__ float hsum4(float4 a){ return a.x+a.y+a.z+a.w; }
__device__ __forceinline__ void splitpair(float x, float y, uint32_t& hi, uint32_t& lo){
    __nv_bfloat162 h = __floats2bfloat162_rn(x, y);
    __nv_bfloat162 l = __floats2bfloat162_rn(x - __bfloat162float(h.x), y - __bfloat162float(h.y));
    hi = *reinterpret_cast<uint32_t*>(&h);
    lo = *reinterpret_cast<uint32_t*>(&l);
}

// =====================  CONV STACK (exact R10/R13 versions)  =====================
__global__ __launch_bounds__(256) void conv1_k(const float* __restrict__ x,
        const float* __restrict__ cw, const float* __restrict__ cb, float* __restrict__ out){
    __shared__ float xin[66*30];
    __shared__ float w_s[36];
    __shared__ float b_s[4];
    int b = blockIdx.x/6, pho0 = (blockIdx.x%6)*32;
    int tid = threadIdx.x, lane = tid&31, warp = tid>>5;
    for(int f=tid; f<66*30; f+=256){
        int rr=f/30, cc=f%30;
        int gr=pho0*2-1+rr, gc=cc-1;
        float v=0.f;
        if(gr>=0 && gr<384 && gc>=0 && gc<28) v = x[((size_t)b*384+gr)*28+gc];
        xin[f]=v;
    }
    if(tid<36) w_s[tid]=cw[tid];
    if(tid<4)  b_s[tid]=cb[tid];
    __syncthreads();
    int wo = min(lane,27);
    for(int it=warp; it<128; it+=8){
        int oc=it>>5, ph=it&31;
        float wr[9];
        #pragma unroll
        for(int k=0;k<9;k++) wr[k]=w_s[oc*9+k];
        float bv=b_s[oc], s0=bv, s1=bv;
        #pragma unroll
        for(int kw=0;kw<3;kw++){
            float X[4];
            #pragma unroll
            for(int r=0;r<4;r++) X[r]=xin[(2*ph+r)*30+wo+kw];
            #pragma unroll
            for(int kh=0;kh<3;kh++){
                s0=fmaf(X[kh],  wr[kh*3+kw],s0);
                s1=fmaf(X[kh+1],wr[kh*3+kw],s1);
            }
        }
        float m = fmaxf(fmaxf(s0,0.f), fmaxf(s1,0.f));
        if(lane<28) out[((size_t)(b*4+oc)*192+pho0+ph)*28+wo]=m;
    }
}

__global__ __launch_bounds__(256) void conv2_k(const float* __restrict__ in,
        const float* __restrict__ cw, const float* __restrict__ cb, float* __restrict__ out){
    __shared__ float4 xin[34*30];
    __shared__ float4 w_s[144];
    __shared__ float  b_s[16];
    int b = blockIdx.x/6, pho0 = (blockIdx.x%6)*16;
    int tid = threadIdx.x, lane = tid&31, warp = tid>>5;
    for(int f=tid; f<34*30; f+=256){
        int rr=f/30, cc=f%30;
        int gr=pho0*2-1+rr, gc=cc-1;
        float4 v={0,0,0,0};
        if(gr>=0 && gr<192 && gc>=0 && gc<28){
            const float* p = in + ((size_t)b*4*192+gr)*28+gc;
            v.x=p[0]; v.y=p[192*28]; v.z=p[2*192*28]; v.w=p[3*192*28];
        }
        xin[f]=v;
    }
    for(int f=tid; f<144; f+=256){
        int oc=f/9, k=f%9;
        float4 v; v.x=cw[(oc*4+0)*9+k]; v.y=cw[(oc*4+1)*9+k];
                  v.z=cw[(oc*4+2)*9+k]; v.w=cw[(oc*4+3)*9+k];
        w_s[f]=v;
    }
    if(tid<16) b_s[tid]=cb[tid];
    __syncthreads();
    int wc = min(lane,27);
    int oc0 = warp, oc1 = warp+8;
    float bv0 = b_s[oc0], bv1 = b_s[oc1];
    #pragma unroll 1
    for(int pp=0; pp<8; pp++){
        float4 a[2][4];
        #pragma unroll
        for(int o=0;o<2;o++)
            #pragma unroll
            for(int r=0;r<4;r++) a[o][r]=make_float4(0,0,0,0);
        #pragma unroll
        for(int kw=0;kw<3;kw++){
            float4 X[6];
            #pragma unroll
            for(int r=0;r<6;r++) X[r]=xin[(pp*4+r)*30+wc+kw];
            #pragma unroll
            for(int kh=0;kh<3;kh++){
                float4 w0=w_s[oc0*9+kh*3+kw];
                float4 w1=w_s[oc1*9+kh*3+kw];
                ffma4p(a[0][0],X[kh],w0); ffma4p(a[0][1],X[kh+1],w0);
                ffma4p(a[0][2],X[kh+2],w0); ffma4p(a[0][3],X[kh+3],w0);
                ffma4p(a[1][0],X[kh],w1); ffma4p(a[1][1],X[kh+1],w1);
                ffma4p(a[1][2],X[kh+2],w1); ffma4p(a[1][3],X[kh+3],w1);
            }
        }
        #pragma unroll
        for(int o=0;o<2;o++){
            int oc = o ? oc1 : oc0;
            float bv = o ? bv1 : bv0;
            float s0=hsum4(a[o][0])+bv, s1=hsum4(a[o][1])+bv;
            float s2=hsum4(a[o][2])+bv, s3=hsum4(a[o][3])+bv;
            float p0=fmaxf(fmaxf(s0,0.f),fmaxf(s1,0.f));
            float p1=fmaxf(fmaxf(s2,0.f),fmaxf(s3,0.f));
            float q0=fmaxf(p0, __shfl_down_sync(0xffffffffu,p0,1));
            float q1=fmaxf(p1, __shfl_down_sync(0xffffffffu,p1,1));
            if(!(lane&1) && lane<28){
                int wo=wc>>1;
                out[((size_t)(b*16+oc)*96+pho0+2*pp+0)*14+wo]=q0;
                out[((size_t)(b*16+oc)*96+pho0+2*pp+1)*14+wo]=q1;
            }
        }
    }
}

__global__ __launch_bounds__(256) void conv3_k(const float* __restrict__ in,
        const float* __restrict__ cw, const float* __restrict__ cb, float* __restrict__ out){
    __shared__ float4 xin[4*26*16];
    __shared__ float4 w_s[576];
    __shared__ float  b_s[16];
    int b = blockIdx.x>>2, pho0 = (blockIdx.x&3)*8;
    int tid = threadIdx.x, lane = tid&31, warp = tid>>5;
    for(int f=tid; f<4*26*16; f+=256){
        int icg=f/(26*16), rr=(f/16)%26, cc=f%16;
        int gr=pho0*3-1+rr, gc=cc-1;
        float4 v={0,0,0,0};
        if(gr>=0 && gr<96 && gc>=0 && gc<14){
            const float* p = in + ((size_t)(b*16+icg*4)*96+gr)*14+gc;
            v.x=p[0]; v.y=p[96*14]; v.z=p[2*96*14]; v.w=p[3*96*14];
        }
        xin[f]=v;
    }
    for(int f=tid; f<576; f+=256){
        int oc=f/36, icg=(f/9)%4, k=f%9;
        float4 v;
        v.x=cw[(oc*16+icg*4+0)*9+k]; v.y=cw[(oc*16+icg*4+1)*9+k];
        v.z=cw[(oc*16+icg*4+2)*9+k]; v.w=cw[(oc*16+icg*4+3)*9+k];
        w_s[f]=v;
    }
    if(tid<16) b_s[tid]=cb[tid];
    __syncthreads();
    int half = lane>>4;
    int hw = warp*2 + half;
    int wc = min(lane&15, 13);
    #pragma unroll 1
    for(int it=hw; it<64; it+=16){
        int pair = it>>3, ph = it&7;
        int oc0 = pair, oc1 = pair+8;
        float4 acc[2][3];
        #pragma unroll
        for(int o=0;o<2;o++)
            #pragma unroll
            for(int r=0;r<3;r++) acc[o][r]=make_float4(0,0,0,0);
        #pragma unroll
        for(int icg=0;icg<4;icg++){
            #pragma unroll
            for(int kw=0;kw<3;kw++){
                float4 X[5];
                #pragma unroll
                for(int r=0;r<5;r++) X[r]=xin[(icg*26+3*ph+r)*16+wc+kw];
                #pragma unroll
                for(int kh=0;kh<3;kh++){
                    float4 w0=w_s[(oc0*4+icg)*9+kh*3+kw];
                    float4 w1=w_s[(oc1*4+icg)*9+kh*3+kw];
                    ffma4p(acc[0][0],X[kh],w0);
                    ffma4p(acc[0][1],X[kh+1],w0);
                    ffma4p(acc[0][2],X[kh+2],w0);
                    ffma4p(acc[1][0],X[kh],w1);
                    ffma4p(acc[1][1],X[kh+1],w1);
                    ffma4p(acc[1][2],X[kh+2],w1);
                }
            }
        }
        #pragma unroll
        for(int o=0;o<2;o++){
            int oc = o ? oc1 : oc0;
            float bv = b_s[oc];
            float s0=fmaxf(hsum4(acc[o][0])+bv,0.f);
            float s1=fmaxf(hsum4(acc[o][1])+bv,0.f);
            float s2=fmaxf(hsum4(acc[o][2])+bv,0.f);
            float v=fmaxf(fmaxf(s0,s1),s2);
            float ov=fmaxf(v, __shfl_down_sync(0xffffffffu,v,1));
            if(!(lane&1) && (lane&15)<14)
                out[((size_t)(b*16+oc)*32+pho0+ph)*7+(wc>>1)]=ov;
        }
    }
}

__global__ __launch_bounds__(256) void conv4_k(const float* __restrict__ in,
        const float* __restrict__ cw, const float* __restrict__ cb, float* __restrict__ out){
    __shared__ float4 xin[4*34*9];
    __shared__ float4 w_s[1152];
    __shared__ float  b_s[32];
    int b = blockIdx.x;
    int tid = threadIdx.x, lane = tid&31, warp = tid>>5;
    for(int f=tid; f<4*34*9; f+=256){
        int icg=f/(34*9), rr=(f/9)%34, cc=f%9;
        int gr=rr-1, gc=cc-1;
        float4 v={0,0,0,0};
        if(gr>=0 && gr<32 && gc>=0 && gc<7){
            const float* p = in + ((size_t)(b*16+icg*4)*32+gr)*7+gc;
            v.x=p[0]; v.y=p[32*7]; v.z=p[2*32*7]; v.w=p[3*32*7];
        }
        xin[f]=v;
    }
    for(int f=tid; f<1152; f+=256){
        int oc=f/36, icg=(f/9)%4, k=f%9;
        float4 v;
        v.x=cw[(oc*16+icg*4+0)*9+k]; v.y=cw[(oc*16+icg*4+1)*9+k];
        v.z=cw[(oc*16+icg*4+2)*9+k]; v.w=cw[(oc*16+icg*4+3)*9+k];
        w_s[f]=v;
    }
    if(tid<32) b_s[tid]=cb[tid];
    __syncthreads();
    int quarter = lane>>3;
    int qw = warp*4 + quarter;
    int wc = min(lane&7, 6);
    #pragma unroll 1
    for(int it=qw; it<128; it+=32){
        int pair = it>>3, hq = it&7;
        int oc0 = pair, oc1 = pair+16;
        float4 ac[2][4];
        #pragma unroll
        for(int o=0;o<2;o++)
            #pragma unroll
            for(int r=0;r<4;r++) ac[o][r]=make_float4(0,0,0,0);
        #pragma unroll
        for(int icg=0;icg<4;icg++){
            #pragma unroll
            for(int kw=0;kw<3;kw++){
                float4 X[6];
                #pragma unroll
                for(int r=0;r<6;r++) X[r]=xin[(icg*34+4*hq+r)*9+wc+kw];
                #pragma unroll
                for(int kh=0;kh<3;kh++){
                    float4 w0=w_s[(oc0*4+icg)*9+kh*3+kw];
                    float4 w1=w_s[(oc1*4+icg)*9+kh*3+kw];
                    #pragma unroll
                    for(int r=0;r<4;r++) ffma4p(ac[0][r],X[r+kh],w0);
                    #pragma unroll
                    for(int r=0;r<4;r++) ffma4p(ac[1][r],X[r+kh],w1);
                }
            }
        }
        #pragma unroll
        for(int o=0;o<2;o++){
            int oc = o ? oc1 : oc0;
            float bv = b_s[oc];
            #pragma unroll
            for(int r=0;r<4;r++){
                float s=fmaxf(hsum4(ac[o][r])+bv,0.f);
                if((lane&7)<7)
                    out[((size_t)b*32+hq*4+r)*224+wc*32+oc]=s;
            }
        }
    }
}

// =====================  merged prep kernel  =====================
#define SEG0 100352            // lstmWih 896*112
#define SEG1 (SEG0+100352)     // lstmWhh 896*112
#define SEG2 (SEG1+114688)     // decWih 1024*112
#define SEG3 (SEG2+131072)     // decWhh 1024*128
#define SEG4 (SEG3+896)
#define SEG5 (SEG4+1024)
__global__ void prep_k(const float* __restrict__ lstmWih, const float* __restrict__ lstmWhh,
        const float* __restrict__ decWih, const float* __restrict__ decWhh,
        const float* __restrict__ lstmbih, const float* __restrict__ lstmbhh,
        const float* __restrict__ decbih, const float* __restrict__ decbhh){
    int idx = blockIdx.x*blockDim.x+threadIdx.x;
    if(idx >= SEG5) return;
    if(idx < SEG3){
        const float* W; uint32_t *Wh, *Wl;
        int base, kp2, gatesize;
        if(idx < SEG0){ W=lstmWih; Wh=g_WihH;  Wl=g_WihL;  base=0;    kp2=112; gatesize=224; }
        else if(idx < SEG1){ W=lstmWhh; Wh=g_WhhH;  Wl=g_WhhL;  base=SEG0; kp2=112; gatesize=224; }
        else if(idx < SEG2){ W=decWih;  Wh=g_WdihH; Wl=g_WdihL; base=SEG1; kp2=112; gatesize=256; }
        else { W=decWhh; Wh=g_WdhhH; Wl=g_WdhhL; base=SEG2; kp2=128; gatesize=256; }
        int li = idx - base;
        int kp = li%kp2, np = li/kp2;
        int Ksrc = kp2*2;
        int j=np>>2, gg=np&3;
        int srow = gg*gatesize+j;
        float x = W[(size_t)srow*Ksrc+2*kp], y = W[(size_t)srow*Ksrc+2*kp+1];
        uint32_t h,l; splitpair(x,y,h,l);
        Wh[(size_t)np*kp2+kp]=h; Wl[(size_t)np*kp2+kp]=l;
    } else if(idx < SEG4){
        int np = idx - SEG3;
        int j=np>>2, gg=np&3, s=gg*224+j;
        g_bsE[np] = lstmbih[s]+lstmbhh[s];
    } else {
        int np = idx - SEG4;
        int j=np>>2, gg=np&3, s=gg*256+j;
        g_bsD[np] = decbih[s]+decbhh[s];
    }
}

__global__ void split_a_k(const float* __restrict__ A, uint32_t* __restrict__ Ahi,
                          uint32_t* __restrict__ Alo, int total){
    int idx = blockIdx.x*blockDim.x+threadIdx.x;
    if(idx>=total) return;
    uint32_t h,l; splitpair(A[2*idx], A[2*idx+1], h, l);
    Ahi[idx]=h; Alo[idx]=l;
}
__global__ void init_enc_k(const float* __restrict__ h0, const float* __restrict__ c0){
    int idx = blockIdx.x*blockDim.x+threadIdx.x;
    if(idx < BSZ*AD) g_c[idx] = __ldg(c0 + idx%AD);
    if(idx < BSZ*112){
        int k = idx%112;
        uint32_t h,l; splitpair(__ldg(h0+2*k), __ldg(h0+2*k+1), h, l);
        g_Hh[idx]=h; g_Hl[idx]=l;
    }
}
__global__ void init_dec_k(){
    int idx = blockIdx.x*blockDim.x+threadIdx.x;
    if(idx>=BSZ*HID) return;
    g_dc[idx]=0.f;
    if(idx < BSZ*128){ g_DhH[0][idx]=0u; g_DhL[0][idx]=0u; }
}
__global__ void enc_score_k(const float* __restrict__ att_w){
    int gl = blockIdx.x*blockDim.x+threadIdx.x;
    int row = gl>>5, lane = gl&31;
    if(row>=BSZ*TT) return;
    const float* r = g_y8 + (size_t)row*AD;
    const float* we = att_w + HID;
    float s=0.f;
    for(int k=lane;k<AD;k+=32) s += r[k]*__ldg(we+k);
    #pragma unroll
    for(int o=16;o>0;o>>=1) s += __shfl_xor_sync(0xffffffffu,s,o);
    if(lane==0) g_escore[row]=s;
}

// =====================  one-shot attention (softmax shift-invariance: alpha indep of dh) ===
__global__ __launch_bounds__(256) void attn_once_k(){
    int b = blockIdx.x, tid = threadIdx.x;
    __shared__ float sc[TT];
    __shared__ float ctx_s[AD];
    if(tid < 32){
        float x = g_escore[b*TT + tid];
        float mx = x;
        #pragma unroll
        for(int o=16;o>0;o>>=1) mx = fmaxf(mx,__shfl_xor_sync(0xffffffffu,mx,o));
        float e = expf(x-mx), sm = e;
        #pragma unroll
        for(int o=16;o>0;o>>=1) sm += __shfl_xor_sync(0xffffffffu,sm,o);
        sc[tid] = e/sm;
    }
    __syncthreads();
    if(tid < AD){
        const float* y = g_y8 + (size_t)b*TT*AD + tid;
        float acc=0.f;
        #pragma unroll
        for(int t=0;t<TT;t++) acc = fmaf(sc[t], y[t*AD], acc);
        ctx_s[tid]=acc;
    }
    __syncthreads();
    if(tid < 112){
        uint32_t hh,ll; splitpair(ctx_s[2*tid], ctx_s[2*tid+1], hh, ll);
        g_CtxH[(size_t)b*112 + tid] = hh;
        g_CtxL[(size_t)b*112 + tid] = ll;
    }
}

// =====================  MMA core (256-thread blocks, 8 warps, 64x64 tile)  =====================
#define MMA(c, a, b) asm volatile( \
    "mma.sync.aligned.m16n8k16.row.col.f32.bf16.bf16.f32 " \
    "{%0,%1,%2,%3},{%4,%5,%6,%7},{%8,%9},{%0,%1,%2,%3};" \
    : "+f"(c[0]),"+f"(c[1]),"+f"(c[2]),"+f"(c[3]) \
    : "r"(a[0]),"r"(a[1]),"r"(a[2]),"r"(a[3]),"r"(b[0]),"r"(b[1]))

__device__ __forceinline__ void mma_block(const uint32_t* __restrict__ Ah,
        const uint32_t* __restrict__ Al, const uint32_t* __restrict__ Bh,
        const uint32_t* __restrict__ Bl,
        float (&acc)[2][2][4], int wm, int wn, int g, int tg){
    #pragma unroll
    for(int kk=0;kk<2;kk++){
        uint32_t aH[2][4], aL[2][4], bH[2][2], bL[2][2];
        int kp = kk*8+tg;
        #pragma unroll
        for(int mi=0;mi<2;mi++){
            int r0 = wm*32+mi*16+g;
            aH[mi][0]=Ah[r0*17+kp];   aH[mi][1]=Ah[(r0+8)*17+kp];
            aH[mi][2]=Ah[r0*17+kp+4]; aH[mi][3]=Ah[(r0+8)*17+kp+4];
            aL[mi][0]=Al[r0*17+kp];   aL[mi][1]=Al[(r0+8)*17+kp];
            aL[mi][2]=Al[r0*17+kp+4]; aL[mi][3]=Al[(r0+8)*17+kp+4];
        }
        #pragma unroll
        for(int ni=0;ni<2;ni++){
            int c0 = wn*16+ni*8+g;
            bH[ni][0]=Bh[c0*17+kp]; bH[ni][1]=Bh[c0*17+kp+4];
            bL[ni][0]=Bl[c0*17+kp]; bL[ni][1]=Bl[c0*17+kp+4];
        }
        #pragma unroll
        for(int mi=0;mi<2;mi++)
            #pragma unroll
            for(int ni=0;ni<2;ni++){
                MMA(acc[mi][ni], aH[mi], bH[ni]);
                MMA(acc[mi][ni], aL[mi], bH[ni]);
                MMA(acc[mi][ni], aH[mi], bL[ni]);
            }
    }
}

// ---- double-buffered pipelined mainloop; PDL: B prefetch -> gridsync -> A loads ----
#define BUFSZ (4*64*17)

template<int NCHUNK, bool PDL>
__device__ __forceinline__ void gemm_pipe(
        const uint32_t* __restrict__ AsrcH, const uint32_t* __restrict__ AsrcL, int astr,
        const uint32_t* __restrict__ BsrcH, const uint32_t* __restrict__ BsrcL, int bstr,
        uint32_t* P, float (&acc)[2][2][4], int tid, int wm, int wn, int g, int tg){
    int lr = tid>>2, lkp = (tid&3)*4;
    const uint32_t* pah = AsrcH + (size_t)lr*astr + lkp;
    const uint32_t* pal = AsrcL + (size_t)lr*astr + lkp;
    const uint32_t* pbh = BsrcH + (size_t)lr*bstr + lkp;
    const uint32_t* pbl = BsrcL + (size_t)lr*bstr + lkp;
    uint4 rc = *(const uint4*)pbh;        // weights: step-invariant, safe pre-sync
    uint4 rd = *(const uint4*)pbl;
    if(PDL) cudaGridDependencySynchronize();
    uint4 ra = *(const uint4*)pah;        // activations: depend on predecessor
    uint4 rb = *(const uint4*)pal;
    int o = lr*17 + lkp;
    #pragma unroll
    for(int c=0;c<NCHUNK;c++){
        uint32_t* buf = P + (c&1)*BUFSZ;
        buf[o+0]=ra.x; buf[o+1]=ra.y; buf[o+2]=ra.z; buf[o+3]=ra.w;
        buf[1088+o+0]=rb.x; buf[1088+o+1]=rb.y; buf[1088+o+2]=rb.z; buf[1088+o+3]=rb.w;
        buf[2176+o+0]=rc.x; buf[2176+o+1]=rc.y; buf[2176+o+2]=rc.z; buf[2176+o+3]=rc.w;
        buf[3264+o+0]=rd.x; buf[3264+o+1]=rd.y; buf[3264+o+2]=rd.z; buf[3264+o+3]=rd.w;
        __syncthreads();
        if(c+1<NCHUNK){
            ra = *(const uint4*)(pah + (c+1)*16);
            rb = *(const uint4*)(pal + (c+1)*16);
            rc = *(const uint4*)(pbh + (c+1)*16);
            rd = *(const uint4*)(pbl + (c+1)*16);
        }
        mma_block(buf, buf+1088, buf+2176, buf+3264, acc, wm, wn, g, tg);
    }
}

#define ACC_INIT(acc) { \
    _Pragma("unroll") for(int mi=0;mi<2;mi++) \
        _Pragma("unroll") for(int ni=0;ni<2;ni++) \
            _Pragma("unroll") for(int r=0;r<4;r++) acc[mi][ni][r]=0.f; }

#define ACC_TO_CS(acc, cs) { \
    _Pragma("unroll") for(int mi=0;mi<2;mi++){ \
        int r0 = wm*32+mi*16+g; \
        _Pragma("unroll") for(int ni=0;ni<2;ni++){ \
            int c0c = wn*16+ni*8+tg*2; \
            cs[r0*66+c0c]=acc[mi][ni][0];     cs[r0*66+c0c+1]=acc[mi][ni][1]; \
            cs[(r0+8)*66+c0c]=acc[mi][ni][2]; cs[(r0+8)*66+c0c+1]=acc[mi][ni][3]; \
        } } }

// =====================  xW GEMM (one-shot)  =====================
__global__ __launch_bounds__(256) void gemm_x(){
    __shared__ uint32_t P[2*BUFSZ];
    int tid=threadIdx.x;
    int m0=blockIdx.y*64, n0=blockIdx.x*64;
    int warp=tid>>5, lane=tid&31;
    int wm=warp>>2, wn=warp&3, g=lane>>2, tg=lane&3;
    float acc[2][2][4];
    ACC_INIT(acc);
    gemm_pipe<7,false>(g_Y5h + (size_t)m0*112, g_Y5l + (size_t)m0*112, 112,
                 g_WihH + (size_t)n0*112, g_WihL + (size_t)n0*112, 112,
                 P, acc, tid, wm, wn, g, tg);
    #pragma unroll
    for(int mi=0;mi<2;mi++){
        int row = m0+wm*32+mi*16+g;
        #pragma unroll
        for(int ni=0;ni<2;ni++){
            int col = n0+wn*16+ni*8+tg*2;
            float* p0 = g_xW + (size_t)row*896 + col;
            float* p1 = g_xW + (size_t)(row+8)*896 + col;
            p0[0]=acc[mi][ni][0]; p0[1]=acc[mi][ni][1];
            p1[0]=acc[mi][ni][2]; p1[1]=acc[mi][ni][3];
        }
    }
}

// =====================  ctxW GEMM (one-shot): ctx @ decWih^T + bsD  =====================
__global__ __launch_bounds__(256) void gemm_cw(){
    __shared__ uint32_t P[2*BUFSZ];
    int tid=threadIdx.x;
    int m0=blockIdx.y*64, n0=blockIdx.x*64;
    int warp=tid>>5, lane=tid&31;
    int wm=warp>>2, wn=warp&3, g=lane>>2, tg=lane&3;
    float acc[2][2][4];
    ACC_INIT(acc);
    gemm_pipe<7,false>(g_CtxH + (size_t)m0*112, g_CtxL + (size_t)m0*112, 112,
                 g_WdihH + (size_t)n0*112, g_WdihL + (size_t)n0*112, 112,
                 P, acc, tid, wm, wn, g, tg);
    #pragma unroll
    for(int mi=0;mi<2;mi++){
        int row = m0+wm*32+mi*16+g;
        #pragma unroll
        for(int ni=0;ni<2;ni++){
            int col = n0+wn*16+ni*8+tg*2;
            float* p0 = g_ctxW + (size_t)row*1024 + col;
            float* p1 = g_ctxW + (size_t)(row+8)*1024 + col;
            p0[0]=acc[mi][ni][0]+__ldg(g_bsD+col);   p0[1]=acc[mi][ni][1]+__ldg(g_bsD+col+1);
            p1[0]=acc[mi][ni][2]+__ldg(g_bsD+col);   p1[1]=acc[mi][ni][3]+__ldg(g_bsD+col+1);
        }
    }
}

// =====================  encoder step (launch per t, PDL)  =====================
__global__ __launch_bounds__(256) void enc_step(int t){
    __shared__ uint32_t P[2*BUFSZ];
    float* cs = (float*)(P + BUFSZ);   // NCHUNK=7: last mma reads buffer 0 -> cs aliases buffer 1
    int tid=threadIdx.x;
    int m0=blockIdx.y*64, n0=blockIdx.x*64;
    int warp=tid>>5, lane=tid&31;
    int wm=warp>>2, wn=warp&3, g=lane>>2, tg=lane&3;
    const uint32_t* srcH = g_Hh + (size_t)(t&1)*(BSZ*112);
    const uint32_t* srcL = g_Hl + (size_t)(t&1)*(BSZ*112);
    uint32_t* dstH = g_Hh + (size_t)((t+1)&1)*(BSZ*112);
    uint32_t* dstL = g_Hl + (size_t)((t+1)&1)*(BSZ*112);
    float acc[2][2][4];
    ACC_INIT(acc);
    gemm_pipe<7,true>(srcH + (size_t)m0*112, srcL + (size_t)m0*112, 112,
                 g_WhhH + (size_t)n0*112, g_WhhL + (size_t)n0*112, 112,
                 P, acc, tid, wm, wn, g, tg);
    ACC_TO_CS(acc, cs);
    __syncthreads();
    #pragma unroll
    for(int p=tid;p<512;p+=256){
        int m = p>>3, jp = p&7;
        int b = m0+m;
        const float* xw = g_xW + ((size_t)b*TT + t)*896 + n0 + 8*jp;
        float4 x0 = *(const float4*)xw;
        float4 x1 = *(const float4*)(xw+4);
        float4 s0 = *(const float4*)(g_bsE + n0 + 8*jp);
        float4 s1 = *(const float4*)(g_bsE + n0 + 8*jp + 4);
        const float* cp = cs + m*66 + 8*jp;
        float gi0=cp[0]+x0.x+s0.x, gf0=cp[1]+x0.y+s0.y, gg0=cp[2]+x0.z+s0.z, go0=cp[3]+x0.w+s0.w;
        float gi1=cp[4]+x1.x+s1.x, gf1=cp[5]+x1.y+s1.y, gg1=cp[6]+x1.z+s1.z, go1=cp[7]+x1.w+s1.w;
        int j0 = (n0>>2) + 2*jp;
        float c0v = g_c[(size_t)b*AD + j0];
        float c1v = g_c[(size_t)b*AD + j0 + 1];
        float cc0 = sigm(gf0)*c0v + sigm(gi0)*tanhf(gg0);
        float cc1 = sigm(gf1)*c1v + sigm(gi1)*tanhf(gg1);
        float h0v = sigm(go0)*tanhf(cc0);
        float h1v = sigm(go1)*tanhf(cc1);
        g_c[(size_t)b*AD + j0]   = cc0;
        g_c[(size_t)b*AD + j0+1] = cc1;
        float* yp = g_y8 + ((size_t)b*TT + t)*AD + j0;
        yp[0]=h0v; yp[1]=h1v;
        uint32_t hh,ll; splitpair(h0v,h1v,hh,ll);
        dstH[(size_t)b*112 + (n0>>3) + jp] = hh;
        dstL[(size_t)b*112 + (n0>>3) + jp] = ll;
    }
}

// =====================  decoder step: dh@Whh^T only (K=256), PDL  =====================
__global__ __launch_bounds__(256) void dec_step(int s){
    __shared__ uint32_t P[2*BUFSZ];
    float* cs = (float*)P;             // NCHUNK=8: last mma reads buffer 1 -> cs aliases buffer 0
    int tid=threadIdx.x;
    int m0=blockIdx.y*64, n0=blockIdx.x*64;
    int warp=tid>>5, lane=tid&31;
    int wm=warp>>2, wn=warp&3, g=lane>>2, tg=lane&3;
    const uint32_t* srcH = g_DhH[s&1];
    const uint32_t* srcL = g_DhL[s&1];
    uint32_t* dstH = g_DhH[(s+1)&1];
    uint32_t* dstL = g_DhL[(s+1)&1];
    float acc[2][2][4];
    ACC_INIT(acc);
    gemm_pipe<8,true>(srcH + (size_t)m0*128, srcL + (size_t)m0*128, 128,
                  g_WdhhH + (size_t)n0*128, g_WdhhL + (size_t)n0*128, 128,
                  P, acc, tid, wm, wn, g, tg);
    ACC_TO_CS(acc, cs);
    __syncthreads();
    float* dhh = g_dhh[s];
    #pragma unroll
    for(int p=tid;p<512;p+=256){
        int m = p>>3, jp = p&7;
        int b = m0+m;
        const float* cw = g_ctxW + (size_t)b*1024 + n0 + 8*jp;
        float4 x0 = *(const float4*)cw;
        float4 x1 = *(const float4*)(cw+4);
        const float* cp = cs + m*66 + 8*jp;
        float gi0=cp[0]+x0.x, gf0=cp[1]+x0.y, gg0=cp[2]+x0.z, go0=cp[3]+x0.w;
        float gi1=cp[4]+x1.x, gf1=cp[5]+x1.y, gg1=cp[6]+x1.z, go1=cp[7]+x1.w;
        int j0 = (n0>>2) + 2*jp;
        float c0v = g_dc[(size_t)b*HID + j0];
        float c1v = g_dc[(size_t)b*HID + j0 + 1];
        float cc0 = sigm(gf0)*c0v + sigm(gi0)*tanhf(gg0);
        float cc1 = sigm(gf1)*c1v + sigm(gi1)*tanhf(gg1);
        float h0v = sigm(go0)*tanhf(cc0);
        float h1v = sigm(go1)*tanhf(cc1);
        g_dc[(size_t)b*HID + j0]   = cc0;
        g_dc[(size_t)b*HID + j0+1] = cc1;
        dhh[(size_t)b*HID + j0]    = h0v;
        dhh[(size_t)b*HID + j0+1]  = h1v;
        uint32_t hh,ll; splitpair(h0v,h1v,hh,ll);
        dstH[(size_t)b*128 + (n0>>3) + jp] = hh;
        dstL[(size_t)b*128 + (n0>>3) + jp] = ll;
    }
}

// =====================  batched output projection (all 25 steps)  =====================
__global__ __launch_bounds__(256) void out_all_k(const float* __restrict__ outw,
        const float* __restrict__ outb, float* __restrict__ out){
    int gw = blockIdx.x*8 + (threadIdx.x>>5);
    int lane = threadIdx.x & 31;
    if(gw >= OUT_LEN*BSZ) return;
    int s = gw / BSZ, b = gw % BSZ;
    const float* dh = g_dhh[s] + (size_t)b*HID;
    float dv[8];
    #pragma unroll
    for(int q=0;q<8;q++) dv[q] = dh[lane+32*q];
    #pragma unroll 1
    for(int v=0; v<VOCAB; v++){
        const float* wp = outw + (size_t)v*HID;
        float sum = 0.f;
        #pragma unroll
        for(int q=0;q<8;q++) sum = fmaf(dv[q], __ldg(wp+lane+32*q), sum);
        #pragma unroll
        for(int o=16;o>0;o>>=1) sum += __shfl_xor_sync(0xffffffffu,sum,o);
        if(lane==0)
            out[(size_t)b*VOCAB*OUT_LEN + v*OUT_LEN + s] = sum + __ldg(outb+v);
    }
}

// =====================  launch  =====================
extern "C" void kernel_launch(void* const* d_in, const int* in_sizes, int n_in,
                              void* d_out, int out_size){
    const float* x       = (const float*)d_in[0];
    const float* c1w     = (const float*)d_in[1];
    const float* c1b     = (const float*)d_in[2];
    const float* c2w     = (const float*)d_in[3];
    const float* c2b     = (const float*)d_in[4];
    const float* c3w     = (const float*)d_in[5];
    const float* c3b     = (const float*)d_in[6];
    const float* c4w     = (const float*)d_in[7];
    const float* c4b     = (const float*)d_in[8];
    const float* h0      = (const float*)d_in[9];
    const float* c0      = (const float*)d_in[10];
    const float* lstmWih = (const float*)d_in[11];
    const float* lstmWhh = (const float*)d_in[12];
    const float* lstmbih = (const float*)d_in[13];
    const float* lstmbhh = (const float*)d_in[14];
    const float* attw    = (const float*)d_in[15];
    const float* decWih  = (const float*)d_in[17];
    const float* decWhh  = (const float*)d_in[18];
    const float* decbih  = (const float*)d_in[19];
    const float* decbhh  = (const float*)d_in[20];
    const float* outw    = (const float*)d_in[21];
    const float* outb    = (const float*)d_in[22];
    float* out = (float*)d_out;

    float *y1,*y2,*y3,*y5;
    uint32_t *Y5h,*Y5l;
    cudaGetSymbolAddress((void**)&y1,  g_y1);
    cudaGetSymbolAddress((void**)&y2,  g_y2);
    cudaGetSymbolAddress((void**)&y3,  g_y3);
    cudaGetSymbolAddress((void**)&y5,  g_y5);
    cudaGetSymbolAddress((void**)&Y5h, g_Y5h);
    cudaGetSymbolAddress((void**)&Y5l, g_Y5l);

    // merged weight prep (1 launch)
    prep_k<<<(SEG5+255)/256,256>>>(lstmWih, lstmWhh, decWih, decWhh,
                                   lstmbih, lstmbhh, decbih, decbhh);

    // conv stack
    conv1_k<<<BSZ*6,256>>>(x,  c1w, c1b, y1);
    conv2_k<<<BSZ*6,256>>>(y1, c2w, c2b, y2);
    conv3_k<<<BSZ*4,256>>>(y2, c3w, c3b, y3);
    conv4_k<<<BSZ,  256>>>(y3, c4w, c4b, y5);

    // split y5 then xW GEMM
    split_a_k<<<(BSZ*TT*112+255)/256,256>>>(y5, Y5h, Y5l, BSZ*TT*112);
    gemm_x<<<dim3(14,512),256>>>();

    // encoder scan (PDL launches)
    init_enc_k<<<(BSZ*AD+255)/256,256>>>(h0, c0);
    cudaLaunchAttribute pdlAttr[1];
    pdlAttr[0].id = cudaLaunchAttributeProgrammaticStreamSerialization;
    pdlAttr[0].val.programmaticStreamSerializationAllowed = 1;
    for(int t=0;t<TT;t++){
        cudaLaunchConfig_t cfg = {};
        cfg.gridDim = dim3(14,16);
        cfg.blockDim = dim3(256);
        cfg.attrs = pdlAttr;
        cfg.numAttrs = 1;
        cudaLaunchKernelEx(&cfg, enc_step, t);
    }

    // one-shot attention (alpha indep of decoder state) + ctxW GEMM + decoder init
    enc_score_k<<<(BSZ*TT*32+255)/256,256>>>(attw);
    attn_once_k<<<BSZ,256>>>();
    init_dec_k<<<(BSZ*HID+255)/256,256>>>();
    gemm_cw<<<dim3(16,16),256>>>();

    // decoder scan (PDL launches, 1 kernel/step)
    for(int s=0;s<OUT_LEN;s++){
        cudaLaunchConfig_t cfg = {};
        cfg.gridDim = dim3(16,16);
        cfg.blockDim = dim3(256);
        cfg.attrs = pdlAttr;
        cfg.numAttrs = 1;
        cudaLaunchKernelEx(&cfg, dec_step, s);
    }

    // batched output projection for all steps
    out_all_k<<<(OUT_LEN*BSZ+7)/8,256>>>(outw, outb, out);
}

// round 17
// speedup vs baseline: 1.4997x; 1.0457x over previous
#include <cuda_runtime.h>
#include <cuda_bf16.h>
#include <cstdint>

#define BSZ  1024
#define TT   32
#define AD   224
#define HID  256
#define VOCAB 29
#define OUT_LEN 25

// ---------------- scratch (device globals) ----------------
__device__ float g_y1[BSZ*4*192*28];
__device__ float g_y2[BSZ*16*96*14];
__device__ float g_y3[BSZ*16*32*7];
__device__ float g_y5[BSZ*TT*AD];
__device__ __align__(16) float g_xW[BSZ*TT*896];
__device__ __align__(16) float g_y8[BSZ*TT*AD];
__device__ float g_escore[BSZ*TT];
__device__ float g_c [BSZ*AD];
__device__ float g_dc[BSZ*HID];
__device__ __align__(16) float g_ctxW[BSZ*1024];
__device__ __align__(16) float g_dhh[OUT_LEN][BSZ*HID];
// pre-split activations (bf16 hi/lo pairs packed as u32)
__device__ __align__(16) uint32_t g_Y5h[BSZ*TT*112], g_Y5l[BSZ*TT*112];
__device__ __align__(16) uint32_t g_Hh[2*BSZ*112],   g_Hl[2*BSZ*112];
__device__ __align__(16) uint32_t g_DhH[2][BSZ*128], g_DhL[2][BSZ*128];
__device__ __align__(16) uint32_t g_CtxH[BSZ*112],   g_CtxL[BSZ*112];
// pre-split weights, gate-interleaved rows
__device__ __align__(16) uint32_t g_WihH[896*112],  g_WihL[896*112];
__device__ __align__(16) uint32_t g_WhhH[896*112],  g_WhhL[896*112];
__device__ __align__(16) uint32_t g_WdihH[1024*112], g_WdihL[1024*112];
__device__ __align__(16) uint32_t g_WdhhH[1024*128], g_WdhhL[1024*128];
__device__ __align__(16) float g_bsE[896], g_bsD[1024];

__device__ __forceinline__ float sigm(float x){
    return __fdividef(1.0f, 1.0f + __expf(-x));
}
__device__ __forceinline__ void ffma4p(float4& a, const float4& x, const float4& w){
    unsigned long long* ap = reinterpret_cast<unsigned long long*>(&a);
    const unsigned long long* xp = reinterpret_cast<const unsigned long long*>(&x);
    const unsigned long long* wp = reinterpret_cast<const unsigned long long*>(&w);
    asm("fma.rn.f32x2 %0, %1, %2, %0;" : "+l"(ap[0]) : "l"(xp[0]), "l"(wp[0]));
    asm("fma.rn.f32x2 %0, %1, %2, %0;" : "+l"(ap[1]) : "l"(xp[1]), "l"(wp[1]));
}
__device__ __forceinline__ float hsum4(float4 a){ return a.x+a.y+a.z+a.w; }
__device__ __forceinline__ void splitpair(float x, float y, uint32_t& hi, uint32_t& lo){
    __nv_bfloat162 h = __floats2bfloat162_rn(x, y);
    __nv_bfloat162 l = __floats2bfloat162_rn(x - __bfloat162float(h.x), y - __bfloat162float(h.y));
    hi = *reinterpret_cast<uint32_t*>(&h);
    lo = *reinterpret_cast<uint32_t*>(&l);
}

#define MMA(c, a, b) asm volatile( \
    "mma.sync.aligned.m16n8k16.row.col.f32.bf16.bf16.f32 " \
    "{%0,%1,%2,%3},{%4,%5,%6,%7},{%8,%9},{%0,%1,%2,%3};" \
    : "+f"(c[0]),"+f"(c[1]),"+f"(c[2]),"+f"(c[3]) \
    : "r"(a[0]),"r"(a[1]),"r"(a[2]),"r"(a[3]),"r"(b[0]),"r"(b[1]))

// =====================  CONV STACK  =====================
__global__ __launch_bounds__(256) void conv1_k(const float* __restrict__ x,
        const float* __restrict__ cw, const float* __restrict__ cb, float* __restrict__ out){
    __shared__ float xin[66*30];
    __shared__ float w_s[36];
    __shared__ float b_s[4];
    int b = blockIdx.x/6, pho0 = (blockIdx.x%6)*32;
    int tid = threadIdx.x, lane = tid&31, warp = tid>>5;
    for(int f=tid; f<66*30; f+=256){
        int rr=f/30, cc=f%30;
        int gr=pho0*2-1+rr, gc=cc-1;
        float v=0.f;
        if(gr>=0 && gr<384 && gc>=0 && gc<28) v = x[((size_t)b*384+gr)*28+gc];
        xin[f]=v;
    }
    if(tid<36) w_s[tid]=cw[tid];
    if(tid<4)  b_s[tid]=cb[tid];
    __syncthreads();
    int wo = min(lane,27);
    for(int it=warp; it<128; it+=8){
        int oc=it>>5, ph=it&31;
        float wr[9];
        #pragma unroll
        for(int k=0;k<9;k++) wr[k]=w_s[oc*9+k];
        float bv=b_s[oc], s0=bv, s1=bv;
        #pragma unroll
        for(int kw=0;kw<3;kw++){
            float X[4];
            #pragma unroll
            for(int r=0;r<4;r++) X[r]=xin[(2*ph+r)*30+wo+kw];
            #pragma unroll
            for(int kh=0;kh<3;kh++){
                s0=fmaf(X[kh],  wr[kh*3+kw],s0);
                s1=fmaf(X[kh+1],wr[kh*3+kw],s1);
            }
        }
        float m = fmaxf(fmaxf(s0,0.f), fmaxf(s1,0.f));
        if(lane<28) out[((size_t)(b*4+oc)*192+pho0+ph)*28+wo]=m;
    }
}

__global__ __launch_bounds__(256) void conv2_k(const float* __restrict__ in,
        const float* __restrict__ cw, const float* __restrict__ cb, float* __restrict__ out){
    __shared__ float4 xin[34*30];
    __shared__ float4 w_s[144];
    __shared__ float  b_s[16];
    int b = blockIdx.x/6, pho0 = (blockIdx.x%6)*16;
    int tid = threadIdx.x, lane = tid&31, warp = tid>>5;
    for(int f=tid; f<34*30; f+=256){
        int rr=f/30, cc=f%30;
        int gr=pho0*2-1+rr, gc=cc-1;
        float4 v={0,0,0,0};
        if(gr>=0 && gr<192 && gc>=0 && gc<28){
            const float* p = in + ((size_t)b*4*192+gr)*28+gc;
            v.x=p[0]; v.y=p[192*28]; v.z=p[2*192*28]; v.w=p[3*192*28];
        }
        xin[f]=v;
    }
    for(int f=tid; f<144; f+=256){
        int oc=f/9, k=f%9;
        float4 v; v.x=cw[(oc*4+0)*9+k]; v.y=cw[(oc*4+1)*9+k];
                  v.z=cw[(oc*4+2)*9+k]; v.w=cw[(oc*4+3)*9+k];
        w_s[f]=v;
    }
    if(tid<16) b_s[tid]=cb[tid];
    __syncthreads();
    int wc = min(lane,27);
    int oc0 = warp, oc1 = warp+8;
    float bv0 = b_s[oc0], bv1 = b_s[oc1];
    #pragma unroll 1
    for(int pp=0; pp<8; pp++){
        float4 a[2][4];
        #pragma unroll
        for(int o=0;o<2;o++)
            #pragma unroll
            for(int r=0;r<4;r++) a[o][r]=make_float4(0,0,0,0);
        #pragma unroll
        for(int kw=0;kw<3;kw++){
            float4 X[6];
            #pragma unroll
            for(int r=0;r<6;r++) X[r]=xin[(pp*4+r)*30+wc+kw];
            #pragma unroll
            for(int kh=0;kh<3;kh++){
                float4 w0=w_s[oc0*9+kh*3+kw];
                float4 w1=w_s[oc1*9+kh*3+kw];
                ffma4p(a[0][0],X[kh],w0); ffma4p(a[0][1],X[kh+1],w0);
                ffma4p(a[0][2],X[kh+2],w0); ffma4p(a[0][3],X[kh+3],w0);
                ffma4p(a[1][0],X[kh],w1); ffma4p(a[1][1],X[kh+1],w1);
                ffma4p(a[1][2],X[kh+2],w1); ffma4p(a[1][3],X[kh+3],w1);
            }
        }
        #pragma unroll
        for(int o=0;o<2;o++){
            int oc = o ? oc1 : oc0;
            float bv = o ? bv1 : bv0;
            float s0=hsum4(a[o][0])+bv, s1=hsum4(a[o][1])+bv;
            float s2=hsum4(a[o][2])+bv, s3=hsum4(a[o][3])+bv;
            float p0=fmaxf(fmaxf(s0,0.f),fmaxf(s1,0.f));
            float p1=fmaxf(fmaxf(s2,0.f),fmaxf(s3,0.f));
            float q0=fmaxf(p0, __shfl_down_sync(0xffffffffu,p0,1));
            float q1=fmaxf(p1, __shfl_down_sync(0xffffffffu,p1,1));
            if(!(lane&1) && lane<28){
                int wo=wc>>1;
                out[((size_t)(b*16+oc)*96+pho0+2*pp+0)*14+wo]=q0;
                out[((size_t)(b*16+oc)*96+pho0+2*pp+1)*14+wo]=q1;
            }
        }
    }
}

// conv3 as shift-GEMM on tensor cores (bf16x3).
// Block = (b, 24-row strip). X staged position-major [pos 26x16][icpair], stride 12 u32
// (conflict-free). 9 tap-shift MMAs with K=16 (all ic), N=16 oc, M=336.
__global__ __launch_bounds__(256) void conv3_tc(const float* __restrict__ in,
        const float* __restrict__ cw, const float* __restrict__ cb,
        float* __restrict__ out){
    extern __shared__ uint32_t S[];
    uint32_t* Xh = S;                 // 416*12 = 4992
    uint32_t* Xl = S + 4992;          // 4992
    uint32_t* Bh = S + 9984;          // 9*16*12 = 1728
    uint32_t* Bl = S + 11712;         // 1728
    float*    bs = (float*)(S + 13440); // 16
    int b = blockIdx.x >> 2, rb = blockIdx.x & 3;
    int r0 = rb*24;
    int tid = threadIdx.x, lane = tid&31, warp = tid>>5;
    int g = lane>>2, tg = lane&3;

    // stage X (pre-split bf16 hi/lo, ic-pairs contiguous per position)
    for(int idx = tid; idx < 3328; idx += 256){
        int sc = idx & 15;
        int t1 = idx >> 4;             // 0..207
        int icp = t1 / 26, sr = t1 - icp*26;
        int gr = r0 - 1 + sr, gc = sc - 1;
        float x0=0.f, x1=0.f;
        if(gr>=0 && gr<96 && gc>=0 && gc<14){
            const float* p = in + ((size_t)(b*16 + 2*icp)*96 + gr)*14 + gc;
            x0 = p[0]; x1 = p[96*14];
        }
        uint32_t h,l; splitpair(x0,x1,h,l);
        int pos = sr*16 + sc;
        Xh[pos*12 + icp] = h;
        Xl[pos*12 + icp] = l;
    }
    // stage B: [tap][oc][icpair]
    for(int f = tid; f < 9*16*8; f += 256){
        int icp = f & 7;
        int t1 = f >> 3;               // 0..143
        int oc = t1 & 15, tap = t1 >> 4;
        float w0 = cw[(size_t)(oc*16 + 2*icp)*9 + tap];
        float w1 = cw[(size_t)(oc*16 + 2*icp+1)*9 + tap];
        uint32_t h,l; splitpair(w0,w1,h,l);
        Bh[(tap*16 + oc)*12 + icp] = h;
        Bl[(tap*16 + oc)*12 + icp] = l;
    }
    if(tid<16) bs[tid] = cb[tid];
    __syncthreads();

    // per-warp m16 tiles: t = warp, warp+8, warp+16 (<21)
    float acc[3][2][4];
    #pragma unroll
    for(int i=0;i<3;i++)
        #pragma unroll
        for(int n=0;n<2;n++)
            #pragma unroll
            for(int r=0;r<4;r++) acc[i][n][r]=0.f;
    int base0[3], base1[3];
    #pragma unroll
    for(int i=0;i<3;i++){
        int t = warp + i*8;
        if(t < 21){
            int m0 = t*16 + g;
            int r = m0/14, c = m0 - r*14;
            base0[i] = (r*16 + c)*12;
            int m1 = m0 + 8;
            int r1 = m1/14, c1 = m1 - r1*14;
            base1[i] = (r1*16 + c1)*12;
        } else { base0[i]=0; base1[i]=0; }
    }
    #pragma unroll 1
    for(int tap=0; tap<9; tap++){
        int kh = tap/3, kw = tap - kh*3;
        int soff = (kh*16 + kw)*12;
        uint32_t bh[2][2], bl[2][2];
        #pragma unroll
        for(int n=0;n<2;n++){
            int col = (tap*16 + n*8 + g)*12;
            bh[n][0] = Bh[col + tg]; bh[n][1] = Bh[col + tg+4];
            bl[n][0] = Bl[col + tg]; bl[n][1] = Bl[col + tg+4];
        }
        #pragma unroll
        for(int i=0;i<3;i++){
            if(warp + i*8 < 21){
                uint32_t ah[4], al[4];
                int p0 = base0[i] + soff, p1 = base1[i] + soff;
                ah[0]=Xh[p0+tg]; ah[1]=Xh[p1+tg]; ah[2]=Xh[p0+tg+4]; ah[3]=Xh[p1+tg+4];
                al[0]=Xl[p0+tg]; al[1]=Xl[p1+tg]; al[2]=Xl[p0+tg+4]; al[3]=Xl[p1+tg+4];
                #pragma unroll
                for(int n=0;n<2;n++){
                    MMA(acc[i][n], ah, bh[n]);
                    MMA(acc[i][n], al, bh[n]);
                    MMA(acc[i][n], ah, bl[n]);
                }
            }
        }
    }
    __syncthreads();                  // all MMAs done; alias X region with P
    float* P = (float*)S;             // P[336][17]
    #pragma unroll
    for(int i=0;i<3;i++){
        int t = warp + i*8;
        if(t < 21){
            int m0 = t*16+g, m1 = m0+8;
            #pragma unroll
            for(int n=0;n<2;n++){
                int col = n*8 + tg*2;
                P[m0*17+col]   = acc[i][n][0];
                P[m0*17+col+1] = acc[i][n][1];
                P[m1*17+col]   = acc[i][n][2];
                P[m1*17+col+1] = acc[i][n][3];
            }
        }
    }
    __syncthreads();
    // bias + relu + 3x2 maxpool + write y3[b][oc][32][7]
    for(int o = tid; o < 896; o += 256){
        int oc = o & 15;
        int t1 = o >> 4;               // 0..55
        int pr = t1 / 7, pc = t1 - pr*7;
        float bv = bs[oc];
        float mx = -3.4e38f;
        #pragma unroll
        for(int dr=0;dr<3;dr++)
            #pragma unroll
            for(int dc=0;dc<2;dc++){
                int m = (pr*3+dr)*14 + (pc*2+dc);
                float v = fmaxf(P[m*17+oc] + bv, 0.f);
                mx = fmaxf(mx, v);
            }
        out[((size_t)(b*16+oc)*32 + rb*8 + pr)*7 + pc] = mx;
    }
}

__global__ __launch_bounds__(256) void conv4_k(const float* __restrict__ in,
        const float* __restrict__ cw, const float* __restrict__ cb, float* __restrict__ out){
    __shared__ float4 xin[4*34*9];
    __shared__ float4 w_s[1152];
    __shared__ float  b_s[32];
    int b = blockIdx.x;
    int tid = threadIdx.x, lane = tid&31, warp = tid>>5;
    for(int f=tid; f<4*34*9; f+=256){
        int icg=f/(34*9), rr=(f/9)%34, cc=f%9;
        int gr=rr-1, gc=cc-1;
        float4 v={0,0,0,0};
        if(gr>=0 && gr<32 && gc>=0 && gc<7){
            const float* p = in + ((size_t)(b*16+icg*4)*32+gr)*7+gc;
            v.x=p[0]; v.y=p[32*7]; v.z=p[2*32*7]; v.w=p[3*32*7];
        }
        xin[f]=v;
    }
    for(int f=tid; f<1152; f+=256){
        int oc=f/36, icg=(f/9)%4, k=f%9;
        float4 v;
        v.x=cw[(oc*16+icg*4+0)*9+k]; v.y=cw[(oc*16+icg*4+1)*9+k];
        v.z=cw[(oc*16+icg*4+2)*9+k]; v.w=cw[(oc*16+icg*4+3)*9+k];
        w_s[f]=v;
    }
    if(tid<32) b_s[tid]=cb[tid];
    __syncthreads();
    int quarter = lane>>3;
    int qw = warp*4 + quarter;
    int wc = min(lane&7, 6);
    #pragma unroll 1
    for(int it=qw; it<128; it+=32){
        int pair = it>>3, hq = it&7;
        int oc0 = pair, oc1 = pair+16;
        float4 ac[2][4];
        #pragma unroll
        for(int o=0;o<2;o++)
            #pragma unroll
            for(int r=0;r<4;r++) ac[o][r]=make_float4(0,0,0,0);
        #pragma unroll
        for(int icg=0;icg<4;icg++){
            #pragma unroll
            for(int kw=0;kw<3;kw++){
                float4 X[6];
                #pragma unroll
                for(int r=0;r<6;r++) X[r]=xin[(icg*34+4*hq+r)*9+wc+kw];
                #pragma unroll
                for(int kh=0;kh<3;kh++){
                    float4 w0=w_s[(oc0*4+icg)*9+kh*3+kw];
                    float4 w1=w_s[(oc1*4+icg)*9+kh*3+kw];
                    #pragma unroll
                    for(int r=0;r<4;r++) ffma4p(ac[0][r],X[r+kh],w0);
                    #pragma unroll
                    for(int r=0;r<4;r++) ffma4p(ac[1][r],X[r+kh],w1);
                }
            }
        }
        #pragma unroll
        for(int o=0;o<2;o++){
            int oc = o ? oc1 : oc0;
            float bv = b_s[oc];
            #pragma unroll
            for(int r=0;r<4;r++){
                float s=fmaxf(hsum4(ac[o][r])+bv,0.f);
                if((lane&7)<7)
                    out[((size_t)b*32+hq*4+r)*224+wc*32+oc]=s;
            }
        }
    }
}

// =====================  merged prep kernel  =====================
#define SEG0 100352
#define SEG1 (SEG0+100352)
#define SEG2 (SEG1+114688)
#define SEG3 (SEG2+131072)
#define SEG4 (SEG3+896)
#define SEG5 (SEG4+1024)
__global__ void prep_k(const float* __restrict__ lstmWih, const float* __restrict__ lstmWhh,
        const float* __restrict__ decWih, const float* __restrict__ decWhh,
        const float* __restrict__ lstmbih, const float* __restrict__ lstmbhh,
        const float* __restrict__ decbih, const float* __restrict__ decbhh){
    int idx = blockIdx.x*blockDim.x+threadIdx.x;
    if(idx >= SEG5) return;
    if(idx < SEG3){
        const float* W; uint32_t *Wh, *Wl;
        int base, kp2, gatesize;
        if(idx < SEG0){ W=lstmWih; Wh=g_WihH;  Wl=g_WihL;  base=0;    kp2=112; gatesize=224; }
        else if(idx < SEG1){ W=lstmWhh; Wh=g_WhhH;  Wl=g_WhhL;  base=SEG0; kp2=112; gatesize=224; }
        else if(idx < SEG2){ W=decWih;  Wh=g_WdihH; Wl=g_WdihL; base=SEG1; kp2=112; gatesize=256; }
        else { W=decWhh; Wh=g_WdhhH; Wl=g_WdhhL; base=SEG2; kp2=128; gatesize=256; }
        int li = idx - base;
        int kp = li%kp2, np = li/kp2;
        int Ksrc = kp2*2;
        int j=np>>2, gg=np&3;
        int srow = gg*gatesize+j;
        float x = W[(size_t)srow*Ksrc+2*kp], y = W[(size_t)srow*Ksrc+2*kp+1];
        uint32_t h,l; splitpair(x,y,h,l);
        Wh[(size_t)np*kp2+kp]=h; Wl[(size_t)np*kp2+kp]=l;
    } else if(idx < SEG4){
        int np = idx - SEG3;
        int j=np>>2, gg=np&3, s=gg*224+j;
        g_bsE[np] = lstmbih[s]+lstmbhh[s];
    } else {
        int np = idx - SEG4;
        int j=np>>2, gg=np&3, s=gg*256+j;
        g_bsD[np] = decbih[s]+decbhh[s];
    }
}

__global__ void split_a_k(const float* __restrict__ A, uint32_t* __restrict__ Ahi,
                          uint32_t* __restrict__ Alo, int total){
    int idx = blockIdx.x*blockDim.x+threadIdx.x;
    if(idx>=total) return;
    uint32_t h,l; splitpair(A[2*idx], A[2*idx+1], h, l);
    Ahi[idx]=h; Alo[idx]=l;
}
__global__ void init_enc_k(const float* __restrict__ h0, const float* __restrict__ c0){
    int idx = blockIdx.x*blockDim.x+threadIdx.x;
    if(idx < BSZ*AD) g_c[idx] = __ldg(c0 + idx%AD);
    if(idx < BSZ*112){
        int k = idx%112;
        uint32_t h,l; splitpair(__ldg(h0+2*k), __ldg(h0+2*k+1), h, l);
        g_Hh[idx]=h; g_Hl[idx]=l;
    }
}
__global__ void init_dec_k(){
    int idx = blockIdx.x*blockDim.x+threadIdx.x;
    if(idx>=BSZ*HID) return;
    g_dc[idx]=0.f;
    if(idx < BSZ*128){ g_DhH[0][idx]=0u; g_DhL[0][idx]=0u; }
}
__global__ void enc_score_k(const float* __restrict__ att_w){
    int gl = blockIdx.x*blockDim.x+threadIdx.x;
    int row = gl>>5, lane = gl&31;
    if(row>=BSZ*TT) return;
    const float* r = g_y8 + (size_t)row*AD;
    const float* we = att_w + HID;
    float s=0.f;
    for(int k=lane;k<AD;k+=32) s += r[k]*__ldg(we+k);
    #pragma unroll
    for(int o=16;o>0;o>>=1) s += __shfl_xor_sync(0xffffffffu,s,o);
    if(lane==0) g_escore[row]=s;
}

__global__ __launch_bounds__(256) void attn_once_k(){
    int b = blockIdx.x, tid = threadIdx.x;
    __shared__ float sc[TT];
    __shared__ float ctx_s[AD];
    if(tid < 32){
        float x = g_escore[b*TT + tid];
        float mx = x;
        #pragma unroll
        for(int o=16;o>0;o>>=1) mx = fmaxf(mx,__shfl_xor_sync(0xffffffffu,mx,o));
        float e = expf(x-mx), sm = e;
        #pragma unroll
        for(int o=16;o>0;o>>=1) sm += __shfl_xor_sync(0xffffffffu,sm,o);
        sc[tid] = e/sm;
    }
    __syncthreads();
    if(tid < AD){
        const float* y = g_y8 + (size_t)b*TT*AD + tid;
        float acc=0.f;
        #pragma unroll
        for(int t=0;t<TT;t++) acc = fmaf(sc[t], y[t*AD], acc);
        ctx_s[tid]=acc;
    }
    __syncthreads();
    if(tid < 112){
        uint32_t hh,ll; splitpair(ctx_s[2*tid], ctx_s[2*tid+1], hh, ll);
        g_CtxH[(size_t)b*112 + tid] = hh;
        g_CtxL[(size_t)b*112 + tid] = ll;
    }
}

// =====================  MMA GEMM core (8 warps, 64x64 tile)  =====================
__device__ __forceinline__ void mma_block(const uint32_t* __restrict__ Ah,
        const uint32_t* __restrict__ Al, const uint32_t* __restrict__ Bh,
        const uint32_t* __restrict__ Bl,
        float (&acc)[2][2][4], int wm, int wn, int g, int tg){
    #pragma unroll
    for(int kk=0;kk<2;kk++){
        uint32_t aH[2][4], aL[2][4], bH[2][2], bL[2][2];
        int kp = kk*8+tg;
        #pragma unroll
        for(int mi=0;mi<2;mi++){
            int r0 = wm*32+mi*16+g;
            aH[mi][0]=Ah[r0*17+kp];   aH[mi][1]=Ah[(r0+8)*17+kp];
            aH[mi][2]=Ah[r0*17+kp+4]; aH[mi][3]=Ah[(r0+8)*17+kp+4];
            aL[mi][0]=Al[r0*17+kp];   aL[mi][1]=Al[(r0+8)*17+kp];
            aL[mi][2]=Al[r0*17+kp+4]; aL[mi][3]=Al[(r0+8)*17+kp+4];
        }
        #pragma unroll
        for(int ni=0;ni<2;ni++){
            int c0 = wn*16+ni*8+g;
            bH[ni][0]=Bh[c0*17+kp]; bH[ni][1]=Bh[c0*17+kp+4];
            bL[ni][0]=Bl[c0*17+kp]; bL[ni][1]=Bl[c0*17+kp+4];
        }
        #pragma unroll
        for(int mi=0;mi<2;mi++)
            #pragma unroll
            for(int ni=0;ni<2;ni++){
                MMA(acc[mi][ni], aH[mi], bH[ni]);
                MMA(acc[mi][ni], aL[mi], bH[ni]);
                MMA(acc[mi][ni], aH[mi], bL[ni]);
            }
    }
}

#define BUFSZ (4*64*17)

template<int NCHUNK, bool PDL>
__device__ __forceinline__ void gemm_pipe(
        const uint32_t* __restrict__ AsrcH, const uint32_t* __restrict__ AsrcL, int astr,
        const uint32_t* __restrict__ BsrcH, const uint32_t* __restrict__ BsrcL, int bstr,
        uint32_t* P, float (&acc)[2][2][4], int tid, int wm, int wn, int g, int tg){
    int lr = tid>>2, lkp = (tid&3)*4;
    const uint32_t* pah = AsrcH + (size_t)lr*astr + lkp;
    const uint32_t* pal = AsrcL + (size_t)lr*astr + lkp;
    const uint32_t* pbh = BsrcH + (size_t)lr*bstr + lkp;
    const uint32_t* pbl = BsrcL + (size_t)lr*bstr + lkp;
    uint4 rc = *(const uint4*)pbh;
    uint4 rd = *(const uint4*)pbl;
    if(PDL) cudaGridDependencySynchronize();
    uint4 ra = *(const uint4*)pah;
    uint4 rb = *(const uint4*)pal;
    int o = lr*17 + lkp;
    #pragma unroll
    for(int c=0;c<NCHUNK;c++){
        uint32_t* buf = P + (c&1)*BUFSZ;
        buf[o+0]=ra.x; buf[o+1]=ra.y; buf[o+2]=ra.z; buf[o+3]=ra.w;
        buf[1088+o+0]=rb.x; buf[1088+o+1]=rb.y; buf[1088+o+2]=rb.z; buf[1088+o+3]=rb.w;
        buf[2176+o+0]=rc.x; buf[2176+o+1]=rc.y; buf[2176+o+2]=rc.z; buf[2176+o+3]=rc.w;
        buf[3264+o+0]=rd.x; buf[3264+o+1]=rd.y; buf[3264+o+2]=rd.z; buf[3264+o+3]=rd.w;
        __syncthreads();
        if(c+1<NCHUNK){
            ra = *(const uint4*)(pah + (c+1)*16);
            rb = *(const uint4*)(pal + (c+1)*16);
            rc = *(const uint4*)(pbh + (c+1)*16);
            rd = *(const uint4*)(pbl + (c+1)*16);
        }
        mma_block(buf, buf+1088, buf+2176, buf+3264, acc, wm, wn, g, tg);
    }
}

#define ACC_INIT(acc) { \
    _Pragma("unroll") for(int mi=0;mi<2;mi++) \
        _Pragma("unroll") for(int ni=0;ni<2;ni++) \
            _Pragma("unroll") for(int r=0;r<4;r++) acc[mi][ni][r]=0.f; }

#define ACC_TO_CS(acc, cs) { \
    _Pragma("unroll") for(int mi=0;mi<2;mi++){ \
        int r0 = wm*32+mi*16+g; \
        _Pragma("unroll") for(int ni=0;ni<2;ni++){ \
            int c0c = wn*16+ni*8+tg*2; \
            cs[r0*66+c0c]=acc[mi][ni][0];     cs[r0*66+c0c+1]=acc[mi][ni][1]; \
            cs[(r0+8)*66+c0c]=acc[mi][ni][2]; cs[(r0+8)*66+c0c+1]=acc[mi][ni][3]; \
        } } }

__global__ __launch_bounds__(256) void gemm_x(){
    __shared__ uint32_t P[2*BUFSZ];
    int tid=threadIdx.x;
    int m0=blockIdx.y*64, n0=blockIdx.x*64;
    int warp=tid>>5, lane=tid&31;
    int wm=warp>>2, wn=warp&3, g=lane>>2, tg=lane&3;
    float acc[2][2][4];
    ACC_INIT(acc);
    gemm_pipe<7,false>(g_Y5h + (size_t)m0*112, g_Y5l + (size_t)m0*112, 112,
                 g_WihH + (size_t)n0*112, g_WihL + (size_t)n0*112, 112,
                 P, acc, tid, wm, wn, g, tg);
    #pragma unroll
    for(int mi=0;mi<2;mi++){
        int row = m0+wm*32+mi*16+g;
        #pragma unroll
        for(int ni=0;ni<2;ni++){
            int col = n0+wn*16+ni*8+tg*2;
            float* p0 = g_xW + (size_t)row*896 + col;
            float* p1 = g_xW + (size_t)(row+8)*896 + col;
            p0[0]=acc[mi][ni][0]; p0[1]=acc[mi][ni][1];
            p1[0]=acc[mi][ni][2]; p1[1]=acc[mi][ni][3];
        }
    }
}

__global__ __launch_bounds__(256) void gemm_cw(){
    __shared__ uint32_t P[2*BUFSZ];
    int tid=threadIdx.x;
    int m0=blockIdx.y*64, n0=blockIdx.x*64;
    int warp=tid>>5, lane=tid&31;
    int wm=warp>>2, wn=warp&3, g=lane>>2, tg=lane&3;
    float acc[2][2][4];
    ACC_INIT(acc);
    gemm_pipe<7,false>(g_CtxH + (size_t)m0*112, g_CtxL + (size_t)m0*112, 112,
                 g_WdihH + (size_t)n0*112, g_WdihL + (size_t)n0*112, 112,
                 P, acc, tid, wm, wn, g, tg);
    #pragma unroll
    for(int mi=0;mi<2;mi++){
        int row = m0+wm*32+mi*16+g;
        #pragma unroll
        for(int ni=0;ni<2;ni++){
            int col = n0+wn*16+ni*8+tg*2;
            float* p0 = g_ctxW + (size_t)row*1024 + col;
            float* p1 = g_ctxW + (size_t)(row+8)*1024 + col;
            p0[0]=acc[mi][ni][0]+__ldg(g_bsD+col);   p0[1]=acc[mi][ni][1]+__ldg(g_bsD+col+1);
            p1[0]=acc[mi][ni][2]+__ldg(g_bsD+col);   p1[1]=acc[mi][ni][3]+__ldg(g_bsD+col+1);
        }
    }
}

__global__ __launch_bounds__(256) void enc_step(int t){
    __shared__ uint32_t P[2*BUFSZ];
    float* cs = (float*)(P + BUFSZ);
    int tid=threadIdx.x;
    int m0=blockIdx.y*64, n0=blockIdx.x*64;
    int warp=tid>>5, lane=tid&31;
    int wm=warp>>2, wn=warp&3, g=lane>>2, tg=lane&3;
    const uint32_t* srcH = g_Hh + (size_t)(t&1)*(BSZ*112);
    const uint32_t* srcL = g_Hl + (size_t)(t&1)*(BSZ*112);
    uint32_t* dstH = g_Hh + (size_t)((t+1)&1)*(BSZ*112);
    uint32_t* dstL = g_Hl + (size_t)((t+1)&1)*(BSZ*112);
    float acc[2][2][4];
    ACC_INIT(acc);
    gemm_pipe<7,true>(srcH + (size_t)m0*112, srcL + (size_t)m0*112, 112,
                 g_WhhH + (size_t)n0*112, g_WhhL + (size_t)n0*112, 112,
                 P, acc, tid, wm, wn, g, tg);
    ACC_TO_CS(acc, cs);
    __syncthreads();
    #pragma unroll
    for(int p=tid;p<512;p+=256){
        int m = p>>3, jp = p&7;
        int b = m0+m;
        const float* xw = g_xW + ((size_t)b*TT + t)*896 + n0 + 8*jp;
        float4 x0 = *(const float4*)xw;
        float4 x1 = *(const float4*)(xw+4);
        float4 s0 = *(const float4*)(g_bsE + n0 + 8*jp);
        float4 s1 = *(const float4*)(g_bsE + n0 + 8*jp + 4);
        const float* cp = cs + m*66 + 8*jp;
        float gi0=cp[0]+x0.x+s0.x, gf0=cp[1]+x0.y+s0.y, gg0=cp[2]+x0.z+s0.z, go0=cp[3]+x0.w+s0.w;
        float gi1=cp[4]+x1.x+s1.x, gf1=cp[5]+x1.y+s1.y, gg1=cp[6]+x1.z+s1.z, go1=cp[7]+x1.w+s1.w;
        int j0 = (n0>>2) + 2*jp;
        float c0v = g_c[(size_t)b*AD + j0];
        float c1v = g_c[(size_t)b*AD + j0 + 1];
        float cc0 = sigm(gf0)*c0v + sigm(gi0)*tanhf(gg0);
        float cc1 = sigm(gf1)*c1v + sigm(gi1)*tanhf(gg1);
        float h0v = sigm(go0)*tanhf(cc0);
        float h1v = sigm(go1)*tanhf(cc1);
        g_c[(size_t)b*AD + j0]   = cc0;
        g_c[(size_t)b*AD + j0+1] = cc1;
        float* yp = g_y8 + ((size_t)b*TT + t)*AD + j0;
        yp[0]=h0v; yp[1]=h1v;
        uint32_t hh,ll; splitpair(h0v,h1v,hh,ll);
        dstH[(size_t)b*112 + (n0>>3) + jp] = hh;
        dstL[(size_t)b*112 + (n0>>3) + jp] = ll;
    }
}

__global__ __launch_bounds__(256) void dec_step(int s){
    __shared__ uint32_t P[2*BUFSZ];
    float* cs = (float*)P;
    int tid=threadIdx.x;
    int m0=blockIdx.y*64, n0=blockIdx.x*64;
    int warp=tid>>5, lane=tid&31;
    int wm=warp>>2, wn=warp&3, g=lane>>2, tg=lane&3;
    const uint32_t* srcH = g_DhH[s&1];
    const uint32_t* srcL = g_DhL[s&1];
    uint32_t* dstH = g_DhH[(s+1)&1];
    uint32_t* dstL = g_DhL[(s+1)&1];
    float acc[2][2][4];
    ACC_INIT(acc);
    gemm_pipe<8,true>(srcH + (size_t)m0*128, srcL + (size_t)m0*128, 128,
                  g_WdhhH + (size_t)n0*128, g_WdhhL + (size_t)n0*128, 128,
                  P, acc, tid, wm, wn, g, tg);
    ACC_TO_CS(acc, cs);
    __syncthreads();
    float* dhh = g_dhh[s];
    #pragma unroll
    for(int p=tid;p<512;p+=256){
        int m = p>>3, jp = p&7;
        int b = m0+m;
        const float* cw = g_ctxW + (size_t)b*1024 + n0 + 8*jp;
        float4 x0 = *(const float4*)cw;
        float4 x1 = *(const float4*)(cw+4);
        const float* cp = cs + m*66 + 8*jp;
        float gi0=cp[0]+x0.x, gf0=cp[1]+x0.y, gg0=cp[2]+x0.z, go0=cp[3]+x0.w;
        float gi1=cp[4]+x1.x, gf1=cp[5]+x1.y, gg1=cp[6]+x1.z, go1=cp[7]+x1.w;
        int j0 = (n0>>2) + 2*jp;
        float c0v = g_dc[(size_t)b*HID + j0];
        float c1v = g_dc[(size_t)b*HID + j0 + 1];
        float cc0 = sigm(gf0)*c0v + sigm(gi0)*tanhf(gg0);
        float cc1 = sigm(gf1)*c1v + sigm(gi1)*tanhf(gg1);
        float h0v = sigm(go0)*tanhf(cc0);
        float h1v = sigm(go1)*tanhf(cc1);
        g_dc[(size_t)b*HID + j0]   = cc0;
        g_dc[(size_t)b*HID + j0+1] = cc1;
        dhh[(size_t)b*HID + j0]    = h0v;
        dhh[(size_t)b*HID + j0+1]  = h1v;
        uint32_t hh,ll; splitpair(h0v,h1v,hh,ll);
        dstH[(size_t)b*128 + (n0>>3) + jp] = hh;
        dstL[(size_t)b*128 + (n0>>3) + jp] = ll;
    }
}

__global__ __launch_bounds__(256) void out_all_k(const float* __restrict__ outw,
        const float* __restrict__ outb, float* __restrict__ out){
    int gw = blockIdx.x*8 + (threadIdx.x>>5);
    int lane = threadIdx.x & 31;
    if(gw >= OUT_LEN*BSZ) return;
    int s = gw / BSZ, b = gw % BSZ;
    const float* dh = g_dhh[s] + (size_t)b*HID;
    float dv[8];
    #pragma unroll
    for(int q=0;q<8;q++) dv[q] = dh[lane+32*q];
    #pragma unroll 1
    for(int v=0; v<VOCAB; v++){
        const float* wp = outw + (size_t)v*HID;
        float sum = 0.f;
        #pragma unroll
        for(int q=0;q<8;q++) sum = fmaf(dv[q], __ldg(wp+lane+32*q), sum);
        #pragma unroll
        for(int o=16;o>0;o>>=1) sum += __shfl_xor_sync(0xffffffffu,sum,o);
        if(lane==0)
            out[(size_t)b*VOCAB*OUT_LEN + v*OUT_LEN + s] = sum + __ldg(outb+v);
    }
}

// =====================  launch  =====================
extern "C" void kernel_launch(void* const* d_in, const int* in_sizes, int n_in,
                              void* d_out, int out_size){
    const float* x       = (const float*)d_in[0];
    const float* c1w     = (const float*)d_in[1];
    const float* c1b     = (const float*)d_in[2];
    const float* c2w     = (const float*)d_in[3];
    const float* c2b     = (const float*)d_in[4];
    const float* c3w     = (const float*)d_in[5];
    const float* c3b     = (const float*)d_in[6];
    const float* c4w     = (const float*)d_in[7];
    const float* c4b     = (const float*)d_in[8];
    const float* h0      = (const float*)d_in[9];
    const float* c0      = (const float*)d_in[10];
    const float* lstmWih = (const float*)d_in[11];
    const float* lstmWhh = (const float*)d_in[12];
    const float* lstmbih = (const float*)d_in[13];
    const float* lstmbhh = (const float*)d_in[14];
    const float* attw    = (const float*)d_in[15];
    const float* decWih  = (const float*)d_in[17];
    const float* decWhh  = (const float*)d_in[18];
    const float* decbih  = (const float*)d_in[19];
    const float* decbhh  = (const float*)d_in[20];
    const float* outw    = (const float*)d_in[21];
    const float* outb    = (const float*)d_in[22];
    float* out = (float*)d_out;

    float *y1,*y2,*y3,*y5;
    uint32_t *Y5h,*Y5l;
    cudaGetSymbolAddress((void**)&y1,  g_y1);
    cudaGetSymbolAddress((void**)&y2,  g_y2);
    cudaGetSymbolAddress((void**)&y3,  g_y3);
    cudaGetSymbolAddress((void**)&y5,  g_y5);
    cudaGetSymbolAddress((void**)&Y5h, g_Y5h);
    cudaGetSymbolAddress((void**)&Y5l, g_Y5l);

    prep_k<<<(SEG5+255)/256,256>>>(lstmWih, lstmWhh, decWih, decWhh,
                                   lstmbih, lstmbhh, decbih, decbhh);

    // conv stack (conv3 on tensor cores)
    conv1_k<<<BSZ*6,256>>>(x,  c1w, c1b, y1);
    conv2_k<<<BSZ*6,256>>>(y1, c2w, c2b, y2);
    const int C3_SMEM = 13456*4;   // 53824 B
    cudaFuncSetAttribute(conv3_tc, cudaFuncAttributeMaxDynamicSharedMemorySize, C3_SMEM);
    conv3_tc<<<BSZ*4,256,C3_SMEM>>>(y2, c3w, c3b, y3);
    conv4_k<<<BSZ,  256>>>(y3, c4w, c4b, y5);

    split_a_k<<<(BSZ*TT*112+255)/256,256>>>(y5, Y5h, Y5l, BSZ*TT*112);
    gemm_x<<<dim3(14,512),256>>>();

    init_enc_k<<<(BSZ*AD+255)/256,256>>>(h0, c0);
    cudaLaunchAttribute pdlAttr[1];
    pdlAttr[0].id = cudaLaunchAttributeProgrammaticStreamSerialization;
    pdlAttr[0].val.programmaticStreamSerializationAllowed = 1;
    for(int t=0;t<TT;t++){
        cudaLaunchConfig_t cfg = {};
        cfg.gridDim = dim3(14,16);
        cfg.blockDim = dim3(256);
        cfg.attrs = pdlAttr;
        cfg.numAttrs = 1;
        cudaLaunchKernelEx(&cfg, enc_step, t);
    }

    enc_score_k<<<(BSZ*TT*32+255)/256,256>>>(attw);
    attn_once_k<<<BSZ,256>>>();
    init_dec_k<<<(BSZ*HID+255)/256,256>>>();
    gemm_cw<<<dim3(16,16),256>>>();

    for(int s=0;s<OUT_LEN;s++){
        cudaLaunchConfig_t cfg = {};
        cfg.gridDim = dim3(16,16);
        cfg.blockDim = dim3(256);
        cfg.attrs = pdlAttr;
        cfg.numAttrs = 1;
        cudaLaunchKernelEx(&cfg, dec_step, s);
    }

    out_all_k<<<(OUT_LEN*BSZ+7)/8,256>>>(outw, outb, out);
}